// round 12
// baseline (speedup 1.0000x reference)
#include <cuda_runtime.h>
#include <cuda_fp16.h>

#define N_NODES 2000
#define N_EDGES 16000
#define BB 4
#define L1D 12
#define IN_DIM 16
#define REF 32
#define HID 32
#define OUTD 16
#define NB (N_NODES*BB)   // 8000
#define MAXDEG 96

typedef unsigned long long u64;
typedef unsigned int u32;

// ---------------- scratch (device globals; no allocation) ----------------
__device__ __half g_sth[NB*384];     // fp16 state, row-major [nb][l*32+h]
__device__ __half g_sthc[NB*512];    // fp16 state, C-fragment order [nb][lane][j*4+i]
__device__ __half g_A1h[NB*1024];    // A1 fp16 (bias incl)  -> pmb (P1)
__device__ __half g_A2h[NB*1024];    // A2 fp16 (bias incl)  -> k_main, [k][h]
__device__ __half g_B1h[NB*1024];    // B1 fp16              -> k_main, [k][h]
__device__ float  g_P1mc[NB*512];    // (P1 + mbs) in C-fragment order, zero-padded
__device__ int    g_counts[N_NODES]; // zero at load; k_scan re-zeroes each replay
__device__ int    g_cursor[N_NODES];
__device__ int    g_offsets[N_NODES+1];
__device__ int    g_sorted[N_EDGES];

// ---------------- f32x2 packed helpers ----------------
__device__ __forceinline__ u64 pk2(float lo, float hi) {
    u64 r; asm("mov.b64 %0, {%1,%2};" : "=l"(r) : "f"(lo), "f"(hi)); return r;
}
__device__ __forceinline__ u64 pk2s(float v) { return pk2(v, v); }
__device__ __forceinline__ void upk2(float& lo, float& hi, u64 v) {
    asm("mov.b64 {%0,%1}, %2;" : "=f"(lo), "=f"(hi) : "l"(v));
}
__device__ __forceinline__ u64 fma2(u64 a, u64 b, u64 c) {
    u64 d; asm("fma.rn.f32x2 %0, %1, %2, %3;" : "=l"(d) : "l"(a), "l"(b), "l"(c)); return d;
}
__device__ __forceinline__ u64 add2(u64 a, u64 b) {
    u64 d; asm("add.rn.f32x2 %0, %1, %2;" : "=l"(d) : "l"(a), "l"(b)); return d;
}
__device__ __forceinline__ u32 h2u(u64 p) {
    float lo, hi; upk2(lo, hi, p);
    __half2 h = __floats2half2_rn(lo, hi);
    return *reinterpret_cast<u32*>(&h);
}

// ---------------- cp.async / ldmatrix / mma helpers ----------------
__device__ __forceinline__ void cpa16(u32 s, const void* g) {
    asm volatile("cp.async.cg.shared.global [%0], [%1], 16;" :: "r"(s), "l"(g));
}
__device__ __forceinline__ void cpcommit() { asm volatile("cp.async.commit_group;"); }
template<int N> __device__ __forceinline__ void cpwait() {
    asm volatile("cp.async.wait_group %0;" :: "n"(N));
}
__device__ __forceinline__ void ldsm4(u32& r0, u32& r1, u32& r2, u32& r3, u32 addr) {
    asm volatile("ldmatrix.sync.aligned.m8n8.x4.shared.b16 {%0,%1,%2,%3}, [%4];"
        : "=r"(r0), "=r"(r1), "=r"(r2), "=r"(r3) : "r"(addr));
}
__device__ __forceinline__ void ldsm4t(u32& r0, u32& r1, u32& r2, u32& r3, u32 addr) {
    asm volatile("ldmatrix.sync.aligned.m8n8.x4.trans.shared.b16 {%0,%1,%2,%3}, [%4];"
        : "=r"(r0), "=r"(r1), "=r"(r2), "=r"(r3) : "r"(addr));
}
__device__ __forceinline__ void mma16816(float& c0, float& c1, float& c2, float& c3,
                                         u32 a0, u32 a1, u32 a2, u32 a3, u32 b0, u32 b1) {
    asm volatile("mma.sync.aligned.m16n8k16.row.col.f32.f16.f16.f32 "
        "{%0,%1,%2,%3}, {%4,%5,%6,%7}, {%8,%9}, {%0,%1,%2,%3};"
        : "+f"(c0), "+f"(c1), "+f"(c2), "+f"(c3)
        : "r"(a0), "r"(a1), "r"(a2), "r"(a3), "r"(b0), "r"(b1));
}

// ---------------- L1: fused state(+hist) | meta GEMM ----------------
__global__ void __launch_bounds__(128) k_statehistmeta(
        const float* __restrict__ x, const float* __restrict__ W_in,
        const float* __restrict__ b_in, const int* __restrict__ dst,
        const float* __restrict__ mk, const float* __restrict__ W,
        const float* __restrict__ bW) {
    __shared__ __align__(16) float shm[9216];
    int t = threadIdx.x;
    int bx = blockIdx.x;

    if (bx < N_NODES) {
        int n = bx;
        float* xs = shm;
        float* ws = shm + 768;
        float* bs = shm + 1280;
        if (t < 8) atomicAdd(&g_counts[dst[8*n + t]], 1);
        for (int i = t; i < IN_DIM*HID; i += 128) ws[i] = W_in[i];
        if (t < HID) bs[t] = b_in[t];
        for (int i = t; i < BB*L1D*IN_DIM; i += 128) {
            int bl = i / IN_DIM, ii = i % IN_DIM;
            int b = bl / L1D, l = bl % L1D;
            xs[i] = x[((b*L1D + l)*N_NODES + n)*IN_DIM + ii];
        }
        __syncthreads();
        for (int o = t; o < BB*L1D*HID; o += 128) {
            int h = o % HID, bl = o / HID;
            float acc = bs[h];
            #pragma unroll
            for (int i = 0; i < IN_DIM; i++)
                acc = fmaf(xs[bl*IN_DIM + i], ws[i*HID + h], acc);
            g_sth[n*(BB*L1D*HID) + o] = __float2half_rn(acc);
        }
        return;
    }

    int m = bx - N_NODES;
    int nb0 = (m % 250) * 32;
    int c0  = (m / 250) * 128;
    bool needB = (c0 < 1024);       // B2 cancels in softmax -> second half A-only
    float* mks = shm;
    float* wA  = shm + 1024;
    float* wB  = shm + 5120;
    for (int i = t; i < 1024; i += 128) {
        int row = i >> 5, r = i & 31;
        int nb = nb0 + row, n = nb >> 2, b = nb & 3;
        mks[i] = mk[(b*N_NODES + n)*REF + r];
    }
    for (int i = t; i < 1024; i += 128) {
        int r = (i*4) >> 7, c = (i*4) & 127;
        *(float4*)&wA[r*128 + c] = *(const float4*)&W[r*2048 + c0 + c];
        if (needB)
            *(float4*)&wB[r*128 + c] = *(const float4*)&W[(r + REF)*2048 + c0 + c];
    }
    __syncthreads();
    int tc = t & 15, tr = t >> 4;
    int row0 = tr * 4, col0 = tc * 8;
    u64 accA[4][4], accB[4][4];
    #pragma unroll
    for (int i = 0; i < 4; i++)
        #pragma unroll
        for (int j = 0; j < 4; j++) { accA[i][j] = 0ull; accB[i][j] = 0ull; }
    if (needB) {
        #pragma unroll 8
        for (int r = 0; r < REF; r++) {
            ulonglong2 wa0 = *(const ulonglong2*)&wA[r*128 + col0];
            ulonglong2 wa1 = *(const ulonglong2*)&wA[r*128 + col0 + 4];
            ulonglong2 wb0 = *(const ulonglong2*)&wB[r*128 + col0];
            ulonglong2 wb1 = *(const ulonglong2*)&wB[r*128 + col0 + 4];
            #pragma unroll
            for (int i = 0; i < 4; i++) {
                u64 a = pk2s(mks[(row0 + i)*32 + r]);
                accA[i][0] = fma2(a, wa0.x, accA[i][0]);
                accA[i][1] = fma2(a, wa0.y, accA[i][1]);
                accA[i][2] = fma2(a, wa1.x, accA[i][2]);
                accA[i][3] = fma2(a, wa1.y, accA[i][3]);
                accB[i][0] = fma2(a, wb0.x, accB[i][0]);
                accB[i][1] = fma2(a, wb0.y, accB[i][1]);
                accB[i][2] = fma2(a, wb1.x, accB[i][2]);
                accB[i][3] = fma2(a, wb1.y, accB[i][3]);
            }
        }
    } else {
        #pragma unroll 8
        for (int r = 0; r < REF; r++) {
            ulonglong2 wa0 = *(const ulonglong2*)&wA[r*128 + col0];
            ulonglong2 wa1 = *(const ulonglong2*)&wA[r*128 + col0 + 4];
            #pragma unroll
            for (int i = 0; i < 4; i++) {
                u64 a = pk2s(mks[(row0 + i)*32 + r]);
                accA[i][0] = fma2(a, wa0.x, accA[i][0]);
                accA[i][1] = fma2(a, wa0.y, accA[i][1]);
                accA[i][2] = fma2(a, wa1.x, accA[i][2]);
                accA[i][3] = fma2(a, wa1.y, accA[i][3]);
            }
        }
    }
    ulonglong2 bv0 = *(const ulonglong2*)&bW[c0 + col0];
    ulonglong2 bv1 = *(const ulonglong2*)&bW[c0 + col0 + 4];
    #pragma unroll
    for (int i = 0; i < 4; i++) {
        int nb = nb0 + row0 + i;
        u64 oa0 = add2(accA[i][0], bv0.x), oa1 = add2(accA[i][1], bv0.y);
        u64 oa2 = add2(accA[i][2], bv1.x), oa3 = add2(accA[i][3], bv1.y);
        uint4 ha = { h2u(oa0), h2u(oa1), h2u(oa2), h2u(oa3) };
        if (needB) {
            int off = nb*1024 + c0 + col0;
            *(uint4*)&g_A1h[off] = ha;
            uint4 hb = { h2u(accB[i][0]), h2u(accB[i][1]), h2u(accB[i][2]), h2u(accB[i][3]) };
            *(uint4*)&g_B1h[off] = hb;
        } else {
            int off = nb*1024 + (c0 - 1024) + col0;
            *(uint4*)&g_A2h[off] = ha;
        }
    }
}

// ---------------- L2: scan (re-zeroes g_counts for next replay) ----------------
__global__ void k_scan() {
    __shared__ int sb[1024];
    int t = threadIdx.x;
    int i0 = 2*t, i1 = 2*t + 1;
    int a0 = (i0 < N_NODES) ? g_counts[i0] : 0;
    int a1 = (i1 < N_NODES) ? g_counts[i1] : 0;
    sb[t] = a0 + a1;
    __syncthreads();
    for (int off = 1; off < 1024; off <<= 1) {
        int v = (t >= off) ? sb[t - off] : 0;
        __syncthreads();
        sb[t] += v;
        __syncthreads();
    }
    int excl = sb[t] - (a0 + a1);
    if (i0 < N_NODES) { g_offsets[i0] = excl;      g_cursor[i0] = excl;      g_counts[i0] = 0; }
    if (i1 < N_NODES) { g_offsets[i1] = excl + a0; g_cursor[i1] = excl + a0; g_counts[i1] = 0; }
    if (t == 1023) g_offsets[N_NODES] = sb[1023];
}

// ---------------- L3: fused pmb (P1mc + sthc fragment repack) + scatter ----------------
__global__ void __launch_bounds__(128) k_pmbscatter(
        const int* __restrict__ dst,
        const float* __restrict__ mk, const float* __restrict__ Wmb,
        const float* __restrict__ bmb) {
    int nb = blockIdx.x, n = nb >> 2, b = nb & 3;
    int t = threadIdx.x;

    if (nb < 500 && t < 32) {
        int e = nb * 32 + t;
        if (e < N_EDGES) {
            int d = dst[e];
            int pos = atomicAdd(&g_cursor[d], 1);
            g_sorted[pos] = e;
        }
    }

    __shared__ float st[384];
    __shared__ float A1[1024];
    __shared__ float p1s[384];
    __shared__ float mks[REF];
    __shared__ float mbsh[HID];
    for (int i = t; i < 192; i += 128) {
        __half2 h = *((const __half2*)&g_sth[nb*384] + i);
        float2 f = __half22float2(h);
        st[2*i] = f.x; st[2*i + 1] = f.y;
    }
    for (int i = t; i < 512; i += 128) {
        __half2 h = *((const __half2*)&g_A1h[(size_t)nb*1024] + i);
        float2 f = __half22float2(h);
        A1[2*i] = f.x; A1[2*i + 1] = f.y;
    }
    if (t < REF) mks[t] = mk[(b*N_NODES + n)*REF + t];
    __syncthreads();
    // mbs (mbd cancels in softmax) + p1 (without mbs; added at repack)
    if (t < HID) {
        float s1 = 0.f;
        #pragma unroll
        for (int r = 0; r < REF; r++)
            s1 = fmaf(mks[r], Wmb[r*HID + t], s1);
        mbsh[t] = s1;
    }
    {
        int h = t & 31, l0 = t >> 5;
        #pragma unroll
        for (int j = 0; j < 3; j++) {
            int l = l0 + 4*j;
            float p1 = 0.f;
            #pragma unroll
            for (int k = 0; k < HID; k++)
                p1 = fmaf(st[l*HID + k], A1[k*32 + h], p1);
            p1s[l*32 + h] = p1;
        }
    }
    __syncthreads();
    // repack to C-fragment order (lane-major, j*4+i), zero rows 12..15
    if (t < 32) {
        int lane = t, r0 = lane >> 2, cb = 2*(lane & 3);
        float vals[16];
        __half hv[16];
        #pragma unroll
        for (int j = 0; j < 4; j++)
            #pragma unroll
            for (int i = 0; i < 4; i++) {
                int row = r0 + ((i >= 2) ? 8 : 0);
                int col = 8*j + cb + (i & 1);
                bool ok = (row < L1D);
                vals[j*4 + i] = ok ? (p1s[row*32 + col] + mbsh[col]) : 0.f;
                hv[j*4 + i] = __float2half_rn(ok ? st[row*32 + col] : 0.f);
            }
        float4* gp = (float4*)&g_P1mc[(size_t)nb*512 + lane*16];
        gp[0] = *(float4*)&vals[0];  gp[1] = *(float4*)&vals[4];
        gp[2] = *(float4*)&vals[8];  gp[3] = *(float4*)&vals[12];
        uint4* gs = (uint4*)&g_sthc[(size_t)nb*512 + lane*16];
        gs[0] = *(uint4*)&hv[0];     gs[1] = *(uint4*)&hv[8];
    }
}

// ---------------- L4: k_main — tensor cores + fragment-ordered epilogue operands ----------------
// per-warp smem (bytes): ssb 2x1024 @0 | A2b 2x2048 @2048 | ssc 2x1024 @6144 | p1c 2x2048 @8192
// B1/dd tiles borrow A2b[0]/ssb[0] as prologue temps (register fragments afterward).
#define PWB 12288
#define SMEM_MAIN (768 + 4*PWB)   // 49920 bytes -> 4 blocks/SM

__global__ void __launch_bounds__(128, 4) k_main(const int* __restrict__ src,
                                                 const float* __restrict__ W_out,
                                                 const float* __restrict__ b_out,
                                                 float* __restrict__ out) {
    extern __shared__ __align__(16) char sh[];
    int* ekeys = (int*)sh;              // 96 ints
    int* slist = (int*)(sh + 384);      // 96 ints

    int t = threadIdx.x, wid = t >> 5, lane = t & 31;
    int n = blockIdx.x, b = wid;
    int nbd = n*4 + b;
    int es = g_offsets[n];
    int deg = g_offsets[n+1] - es;
    int degc = (deg < MAXDEG) ? deg : MAXDEG;

    if (t < degc) ekeys[t] = g_sorted[es + t];

    char* wb = sh + 768 + wid*PWB;
    __half* ssb = (__half*)wb;                 // 2 x 512 halves (ldmatrix A-layout ss)
    __half* A2b = (__half*)(wb + 2048);        // 2 x 1024 halves
    __half* ssc = (__half*)(wb + 6144);        // 2 x 512 halves (C-fragment ss)
    float*  p1c = (float*)(wb + 8192);         // 2 x 512 floats (C-fragment P1m)
    float*  news = (float*)(wb + 2048);        // alias over A2b after loop

    // prologue: B1 into A2b[0] temp, dd into ssb[0] temp; zero ss pad rows (persist)
    {
        const uint4* pb1 = (const uint4*)&g_B1h[(size_t)nbd*1024];
        #pragma unroll
        for (int i = lane; i < 128; i += 32) ((uint4*)A2b)[i] = pb1[i];
        const uint4* pdd = (const uint4*)&g_sth[(size_t)nbd*384];
        if (lane < 32) ((uint4*)ssb)[lane] = pdd[lane];
        if (lane < 16) ((uint4*)ssb)[32 + lane] = pdd[32 + lane];
        uint4 z = {0,0,0,0};
        if (lane < 16) ((uint4*)ssb)[48 + lane] = z;           // rows 12-15 buf0
        if (lane < 16) ((uint4*)(ssb + 512))[48 + lane] = z;   // rows 12-15 buf1
    }
    __syncwarp();

    // fragment-lane geometry
    int qr = lane & 7, q = lane >> 3;
    u32 offM = (u32)((qr + (q & 1)*8)*64 + (q >> 1)*16);
    int r0 = lane >> 2;
    int cbase = 2*(lane & 3);

    u32 sSS = (u32)__cvta_generic_to_shared(ssb);
    u32 sA2 = (u32)__cvta_generic_to_shared(A2b);
    u32 sSC = (u32)__cvta_generic_to_shared(ssc);
    u32 sP1 = (u32)__cvta_generic_to_shared(p1c);

    // fixed fragments from temps
    u32 b1f[2][4][2];
    #pragma unroll
    for (int s = 0; s < 2; s++)
        #pragma unroll
        for (int p = 0; p < 2; p++) {
            u32 r0_, r1_, r2_, r3_;
            ldsm4t(r0_, r1_, r2_, r3_, sA2 + offM + s*1024 + p*32);
            b1f[s][p*2][0] = r0_;   b1f[s][p*2][1] = r1_;
            b1f[s][p*2+1][0] = r2_; b1f[s][p*2+1][1] = r3_;
        }
    u32 ddf[2][4];
    #pragma unroll
    for (int s = 0; s < 2; s++)
        ldsm4(ddf[s][0], ddf[s][1], ddf[s][2], ddf[s][3], sSS + offM + s*32);

    __syncthreads();
    if (t < degc) {
        int key = ekeys[t], r = 0;
        for (int j = 0; j < degc; j++) r += (ekeys[j] < key);
        slist[r] = src[key];
    }
    __syncthreads();

    float den[4][4], num[4][4];
    #pragma unroll
    for (int j = 0; j < 4; j++)
        #pragma unroll
        for (int i = 0; i < 4; i++) { den[j][i] = 0.f; num[j][i] = 0.f; }

    auto stageEdge = [&](int nbs, int v) {
        const char* pa = (const char*)&g_A2h[(size_t)nbs*1024];
        u32 da = sA2 + v*2048;
        #pragma unroll
        for (int r = 0; r < 4; r++) {
            int c = lane + 32*r;
            cpa16(da + c*16, pa + c*16);
        }
        const char* ps = (const char*)&g_sth[(size_t)nbs*384];   // 768B ldmatrix layout
        u32 dsa = sSS + v*1024;
        cpa16(dsa + lane*16, ps + lane*16);
        if (lane < 16) cpa16(dsa + (32+lane)*16, ps + (32+lane)*16);
        const char* pc = (const char*)&g_sthc[(size_t)nbs*512];  // 1024B fragment layout
        u32 dc = sSC + v*1024;
        #pragma unroll
        for (int r = 0; r < 2; r++) {
            int c = lane + 32*r;
            cpa16(dc + c*16, pc + c*16);
        }
        const char* pp = (const char*)&g_P1mc[(size_t)nbs*512];  // 2048B fragment layout
        u32 dp = sP1 + v*2048;
        #pragma unroll
        for (int r = 0; r < 4; r++) {
            int c = lane + 32*r;
            cpa16(dp + c*16, pp + c*16);
        }
    };

    auto computeEdge = [&](int v) {
        u32 ssbase = sSS + v*1024;
        u32 a2base = sA2 + v*2048;
        u32 ssf[2][4];
        #pragma unroll
        for (int s = 0; s < 2; s++)
            ldsm4(ssf[s][0], ssf[s][1], ssf[s][2], ssf[s][3], ssbase + offM + s*32);
        u32 a2f[2][4][2];
        #pragma unroll
        for (int s = 0; s < 2; s++)
            #pragma unroll
            for (int p = 0; p < 2; p++) {
                u32 r0_, r1_, r2_, r3_;
                ldsm4t(r0_, r1_, r2_, r3_, a2base + offM + s*1024 + p*32);
                a2f[s][p*2][0] = r0_;   a2f[s][p*2][1] = r1_;
                a2f[s][p*2+1][0] = r2_; a2f[s][p*2+1][1] = r3_;
            }
        // coalesced fragment-ordered operands
        const uint4* sc = (const uint4*)(ssc + v*512);
        uint4 sr0 = sc[lane*2], sr1 = sc[lane*2 + 1];
        const __half2* h0 = (const __half2*)&sr0;
        const __half2* h1 = (const __half2*)&sr1;
        const float4* pf = (const float4*)(p1c + v*512) + lane*4;
        #pragma unroll
        for (int j = 0; j < 4; j++) {
            float c0 = 0.f, c1 = 0.f, c2 = 0.f, c3 = 0.f;
            mma16816(c0, c1, c2, c3, ssf[0][0], ssf[0][1], ssf[0][2], ssf[0][3],
                     b1f[0][j][0], b1f[0][j][1]);
            mma16816(c0, c1, c2, c3, ssf[1][0], ssf[1][1], ssf[1][2], ssf[1][3],
                     b1f[1][j][0], b1f[1][j][1]);
            mma16816(c0, c1, c2, c3, ddf[0][0], ddf[0][1], ddf[0][2], ddf[0][3],
                     a2f[0][j][0], a2f[0][j][1]);
            mma16816(c0, c1, c2, c3, ddf[1][0], ddf[1][1], ddf[1][2], ddf[1][3],
                     a2f[1][j][0], a2f[1][j][1]);
            float4 pj = pf[j];
            __half2 ha = (j < 2) ? h0[2*j]     : h1[2*(j-2)];
            __half2 hb = (j < 2) ? h0[2*j + 1] : h1[2*(j-2) + 1];
            float2 fa = __half22float2(ha), fb = __half22float2(hb);
            float w0 = __expf(c0 + pj.x);
            float w1 = __expf(c1 + pj.y);
            float w2 = __expf(c2 + pj.z);
            float w3 = __expf(c3 + pj.w);
            den[j][0] += w0; den[j][1] += w1; den[j][2] += w2; den[j][3] += w3;
            num[j][0] = fmaf(w0, fa.x, num[j][0]);
            num[j][1] = fmaf(w1, fa.y, num[j][1]);
            num[j][2] = fmaf(w2, fb.x, num[j][2]);
            num[j][3] = fmaf(w3, fb.y, num[j][3]);
        }
    };

    for (int m = 0; m < degc + 1; m++) {
        if (m < degc) {
            stageEdge(slist[m]*4 + b, m & 1);
            cpcommit();
        }
        if (m > 0) {
            if (m < degc) cpwait<1>(); else cpwait<0>();
            __syncwarp();
            computeEdge((m - 1) & 1);
            __syncwarp();
        }
    }

    // overflow fallback (deg > MAXDEG): synchronous, rare
    for (int i = MAXDEG; i < deg; i++) {
        int nbs = src[g_sorted[es + i]]*4 + b;
        stageEdge(nbs, 0);
        cpcommit();
        cpwait<0>();
        __syncwarp();
        computeEdge(0);
        __syncwarp();
    }
    __syncwarp();

    // finalize softmax into news (aliases A2b; staging dead)
    #pragma unroll
    for (int j = 0; j < 4; j++) {
        int col = 8*j + cbase;
        float d0 = den[j][0], d1 = den[j][1], d2 = den[j][2], d3 = den[j][3];
        float2 lo;
        lo.x = __fdividef(num[j][0], d0 == 0.f ? 1.f : d0);
        lo.y = __fdividef(num[j][1], d1 == 0.f ? 1.f : d1);
        *(float2*)&news[r0*32 + col] = lo;
        if (r0 < 4) {
            float2 hi;
            hi.x = __fdividef(num[j][2], d2 == 0.f ? 1.f : d2);
            hi.y = __fdividef(num[j][3], d3 == 0.f ? 1.f : d3);
            *(float2*)&news[(r0+8)*32 + col] = hi;
        }
    }
    __syncwarp();

    // output projection
    for (int oi = lane; oi < L1D*OUTD; oi += 32) {
        int l = oi >> 4, o = oi & 15;
        float acc = __ldg(&b_out[o]);
        #pragma unroll
        for (int h = 0; h < HID; h++)
            acc = fmaf(news[l*32 + h], __ldg(&W_out[h*16 + o]), acc);
        out[((b*L1D + l)*N_NODES + n)*OUTD + o] = acc;
    }
}

// ---------------- launch ----------------
extern "C" void kernel_launch(void* const* d_in, const int* in_sizes, int n_in,
                              void* d_out, int out_size) {
    const float* long_states = (const float*)d_in[0];
    const float* short_in    = (const float*)d_in[1];
    const int*   src         = (const int*)d_in[2];
    const int*   dst         = (const int*)d_in[3];
    const float* W_in        = (const float*)d_in[4];
    const float* b_in        = (const float*)d_in[5];
    const float* W_metaW     = (const float*)d_in[6];
    const float* b_metaW     = (const float*)d_in[7];
    const float* W_metab     = (const float*)d_in[8];
    const float* b_metab     = (const float*)d_in[9];
    const float* W_out       = (const float*)d_in[10];
    const float* b_out       = (const float*)d_in[11];
    float* out = (float*)d_out;

    cudaFuncSetAttribute(k_main, cudaFuncAttributeMaxDynamicSharedMemorySize, SMEM_MAIN);

    k_statehistmeta<<<N_NODES + 4000, 128>>>(short_in, W_in, b_in, dst,
                                             long_states, W_metaW, b_metaW);
    k_scan<<<1, 1024>>>();
    k_pmbscatter<<<NB, 128>>>(dst, long_states, W_metab, b_metab);
    k_main<<<N_NODES, 128, SMEM_MAIN>>>(src, W_out, b_out, out);
}

// round 13
// speedup vs baseline: 1.0375x; 1.0375x over previous
#include <cuda_runtime.h>
#include <cuda_fp16.h>

#define N_NODES 2000
#define N_EDGES 16000
#define BB 4
#define L1D 12
#define IN_DIM 16
#define REF 32
#define HID 32
#define OUTD 16
#define NB (N_NODES*BB)   // 8000
#define MAXDEG 96

typedef unsigned long long u64;
typedef unsigned int u32;

// ---------------- scratch (device globals; no allocation) ----------------
__device__ __half g_sth[NB*384];     // fp16 state, row-major [nb][l*32+h]
__device__ __half g_A1h[NB*1024];    // A1 fp16 (bias incl)  -> pmb (P1)
__device__ __half g_A2h[NB*1024];    // A2 fp16 (bias incl)  -> k_main, [k][h]
__device__ __half g_B1h[NB*1024];    // B1 fp16              -> k_main, [k][h]
__device__ float  g_P1mc[NB*512];    // (P1 + mbs) in C-fragment order, zero-padded
__device__ int    g_counts[N_NODES]; // zero at load; k_scan re-zeroes each replay
__device__ int    g_cursor[N_NODES];
__device__ int    g_offsets[N_NODES+1];
__device__ int    g_sorted[N_EDGES];

// ---------------- f32x2 packed helpers ----------------
__device__ __forceinline__ u64 pk2(float lo, float hi) {
    u64 r; asm("mov.b64 %0, {%1,%2};" : "=l"(r) : "f"(lo), "f"(hi)); return r;
}
__device__ __forceinline__ u64 pk2s(float v) { return pk2(v, v); }
__device__ __forceinline__ void upk2(float& lo, float& hi, u64 v) {
    asm("mov.b64 {%0,%1}, %2;" : "=f"(lo), "=f"(hi) : "l"(v));
}
__device__ __forceinline__ u64 fma2(u64 a, u64 b, u64 c) {
    u64 d; asm("fma.rn.f32x2 %0, %1, %2, %3;" : "=l"(d) : "l"(a), "l"(b), "l"(c)); return d;
}
__device__ __forceinline__ u64 add2(u64 a, u64 b) {
    u64 d; asm("add.rn.f32x2 %0, %1, %2;" : "=l"(d) : "l"(a), "l"(b)); return d;
}
__device__ __forceinline__ u32 h2u(u64 p) {
    float lo, hi; upk2(lo, hi, p);
    __half2 h = __floats2half2_rn(lo, hi);
    return *reinterpret_cast<u32*>(&h);
}

// ---------------- cp.async / ldmatrix / mma helpers ----------------
__device__ __forceinline__ void cpa16(u32 s, const void* g) {
    asm volatile("cp.async.cg.shared.global [%0], [%1], 16;" :: "r"(s), "l"(g));
}
__device__ __forceinline__ void cpcommit() { asm volatile("cp.async.commit_group;"); }
template<int N> __device__ __forceinline__ void cpwait() {
    asm volatile("cp.async.wait_group %0;" :: "n"(N));
}
__device__ __forceinline__ void ldsm4(u32& r0, u32& r1, u32& r2, u32& r3, u32 addr) {
    asm volatile("ldmatrix.sync.aligned.m8n8.x4.shared.b16 {%0,%1,%2,%3}, [%4];"
        : "=r"(r0), "=r"(r1), "=r"(r2), "=r"(r3) : "r"(addr));
}
__device__ __forceinline__ void ldsm4t(u32& r0, u32& r1, u32& r2, u32& r3, u32 addr) {
    asm volatile("ldmatrix.sync.aligned.m8n8.x4.trans.shared.b16 {%0,%1,%2,%3}, [%4];"
        : "=r"(r0), "=r"(r1), "=r"(r2), "=r"(r3) : "r"(addr));
}
__device__ __forceinline__ void mma16816(float& c0, float& c1, float& c2, float& c3,
                                         u32 a0, u32 a1, u32 a2, u32 a3, u32 b0, u32 b1) {
    asm volatile("mma.sync.aligned.m16n8k16.row.col.f32.f16.f16.f32 "
        "{%0,%1,%2,%3}, {%4,%5,%6,%7}, {%8,%9}, {%0,%1,%2,%3};"
        : "+f"(c0), "+f"(c1), "+f"(c2), "+f"(c3)
        : "r"(a0), "r"(a1), "r"(a2), "r"(a3), "r"(b0), "r"(b1));
}

// ---------------- L1: fused state(+hist) | meta GEMM ----------------
__global__ void __launch_bounds__(128) k_statehistmeta(
        const float* __restrict__ x, const float* __restrict__ W_in,
        const float* __restrict__ b_in, const int* __restrict__ dst,
        const float* __restrict__ mk, const float* __restrict__ W,
        const float* __restrict__ bW) {
    __shared__ __align__(16) float shm[9216];
    int t = threadIdx.x;
    int bx = blockIdx.x;

    if (bx < N_NODES) {
        int n = bx;
        float* xs = shm;
        float* ws = shm + 768;
        float* bs = shm + 1280;
        if (t < 8) atomicAdd(&g_counts[dst[8*n + t]], 1);
        for (int i = t; i < IN_DIM*HID; i += 128) ws[i] = W_in[i];
        if (t < HID) bs[t] = b_in[t];
        for (int i = t; i < BB*L1D*IN_DIM; i += 128) {
            int bl = i / IN_DIM, ii = i % IN_DIM;
            int b = bl / L1D, l = bl % L1D;
            xs[i] = x[((b*L1D + l)*N_NODES + n)*IN_DIM + ii];
        }
        __syncthreads();
        for (int o = t; o < BB*L1D*HID; o += 128) {
            int h = o % HID, bl = o / HID;
            float acc = bs[h];
            #pragma unroll
            for (int i = 0; i < IN_DIM; i++)
                acc = fmaf(xs[bl*IN_DIM + i], ws[i*HID + h], acc);
            g_sth[n*(BB*L1D*HID) + o] = __float2half_rn(acc);
        }
        return;
    }

    int m = bx - N_NODES;
    int nb0 = (m % 250) * 32;
    int c0  = (m / 250) * 128;
    bool needB = (c0 < 1024);       // B2 cancels in softmax -> second half A-only
    float* mks = shm;
    float* wA  = shm + 1024;
    float* wB  = shm + 5120;
    for (int i = t; i < 1024; i += 128) {
        int row = i >> 5, r = i & 31;
        int nb = nb0 + row, n = nb >> 2, b = nb & 3;
        mks[i] = mk[(b*N_NODES + n)*REF + r];
    }
    for (int i = t; i < 1024; i += 128) {
        int r = (i*4) >> 7, c = (i*4) & 127;
        *(float4*)&wA[r*128 + c] = *(const float4*)&W[r*2048 + c0 + c];
        if (needB)
            *(float4*)&wB[r*128 + c] = *(const float4*)&W[(r + REF)*2048 + c0 + c];
    }
    __syncthreads();
    int tc = t & 15, tr = t >> 4;
    int row0 = tr * 4, col0 = tc * 8;
    u64 accA[4][4], accB[4][4];
    #pragma unroll
    for (int i = 0; i < 4; i++)
        #pragma unroll
        for (int j = 0; j < 4; j++) { accA[i][j] = 0ull; accB[i][j] = 0ull; }
    if (needB) {
        #pragma unroll 8
        for (int r = 0; r < REF; r++) {
            ulonglong2 wa0 = *(const ulonglong2*)&wA[r*128 + col0];
            ulonglong2 wa1 = *(const ulonglong2*)&wA[r*128 + col0 + 4];
            ulonglong2 wb0 = *(const ulonglong2*)&wB[r*128 + col0];
            ulonglong2 wb1 = *(const ulonglong2*)&wB[r*128 + col0 + 4];
            #pragma unroll
            for (int i = 0; i < 4; i++) {
                u64 a = pk2s(mks[(row0 + i)*32 + r]);
                accA[i][0] = fma2(a, wa0.x, accA[i][0]);
                accA[i][1] = fma2(a, wa0.y, accA[i][1]);
                accA[i][2] = fma2(a, wa1.x, accA[i][2]);
                accA[i][3] = fma2(a, wa1.y, accA[i][3]);
                accB[i][0] = fma2(a, wb0.x, accB[i][0]);
                accB[i][1] = fma2(a, wb0.y, accB[i][1]);
                accB[i][2] = fma2(a, wb1.x, accB[i][2]);
                accB[i][3] = fma2(a, wb1.y, accB[i][3]);
            }
        }
    } else {
        #pragma unroll 8
        for (int r = 0; r < REF; r++) {
            ulonglong2 wa0 = *(const ulonglong2*)&wA[r*128 + col0];
            ulonglong2 wa1 = *(const ulonglong2*)&wA[r*128 + col0 + 4];
            #pragma unroll
            for (int i = 0; i < 4; i++) {
                u64 a = pk2s(mks[(row0 + i)*32 + r]);
                accA[i][0] = fma2(a, wa0.x, accA[i][0]);
                accA[i][1] = fma2(a, wa0.y, accA[i][1]);
                accA[i][2] = fma2(a, wa1.x, accA[i][2]);
                accA[i][3] = fma2(a, wa1.y, accA[i][3]);
            }
        }
    }
    ulonglong2 bv0 = *(const ulonglong2*)&bW[c0 + col0];
    ulonglong2 bv1 = *(const ulonglong2*)&bW[c0 + col0 + 4];
    #pragma unroll
    for (int i = 0; i < 4; i++) {
        int nb = nb0 + row0 + i;
        u64 oa0 = add2(accA[i][0], bv0.x), oa1 = add2(accA[i][1], bv0.y);
        u64 oa2 = add2(accA[i][2], bv1.x), oa3 = add2(accA[i][3], bv1.y);
        uint4 ha = { h2u(oa0), h2u(oa1), h2u(oa2), h2u(oa3) };
        if (needB) {
            int off = nb*1024 + c0 + col0;
            *(uint4*)&g_A1h[off] = ha;
            uint4 hb = { h2u(accB[i][0]), h2u(accB[i][1]), h2u(accB[i][2]), h2u(accB[i][3]) };
            *(uint4*)&g_B1h[off] = hb;
        } else {
            int off = nb*1024 + (c0 - 1024) + col0;
            *(uint4*)&g_A2h[off] = ha;
        }
    }
}

// ---------------- L2: scan (re-zeroes g_counts for next replay) ----------------
__global__ void k_scan() {
    __shared__ int sb[1024];
    int t = threadIdx.x;
    int i0 = 2*t, i1 = 2*t + 1;
    int a0 = (i0 < N_NODES) ? g_counts[i0] : 0;
    int a1 = (i1 < N_NODES) ? g_counts[i1] : 0;
    sb[t] = a0 + a1;
    __syncthreads();
    for (int off = 1; off < 1024; off <<= 1) {
        int v = (t >= off) ? sb[t - off] : 0;
        __syncthreads();
        sb[t] += v;
        __syncthreads();
    }
    int excl = sb[t] - (a0 + a1);
    if (i0 < N_NODES) { g_offsets[i0] = excl;      g_cursor[i0] = excl;      g_counts[i0] = 0; }
    if (i1 < N_NODES) { g_offsets[i1] = excl + a0; g_cursor[i1] = excl + a0; g_counts[i1] = 0; }
    if (t == 1023) g_offsets[N_NODES] = sb[1023];
}

// ---------------- L3: fused pmb (P1mc fragment repack) + scatter ----------------
__global__ void __launch_bounds__(128) k_pmbscatter(
        const int* __restrict__ dst,
        const float* __restrict__ mk, const float* __restrict__ Wmb,
        const float* __restrict__ bmb) {
    int nb = blockIdx.x, n = nb >> 2, b = nb & 3;
    int t = threadIdx.x;

    if (nb < 500 && t < 32) {
        int e = nb * 32 + t;
        if (e < N_EDGES) {
            int d = dst[e];
            int pos = atomicAdd(&g_cursor[d], 1);
            g_sorted[pos] = e;
        }
    }

    __shared__ float st[384];
    __shared__ float A1[1024];
    __shared__ float p1s[384];
    __shared__ float mks[REF];
    __shared__ float mbsh[HID];
    for (int i = t; i < 192; i += 128) {
        __half2 h = *((const __half2*)&g_sth[nb*384] + i);
        float2 f = __half22float2(h);
        st[2*i] = f.x; st[2*i + 1] = f.y;
    }
    for (int i = t; i < 512; i += 128) {
        __half2 h = *((const __half2*)&g_A1h[(size_t)nb*1024] + i);
        float2 f = __half22float2(h);
        A1[2*i] = f.x; A1[2*i + 1] = f.y;
    }
    if (t < REF) mks[t] = mk[(b*N_NODES + n)*REF + t];
    __syncthreads();
    if (t < HID) {
        float s1 = 0.f;
        #pragma unroll
        for (int r = 0; r < REF; r++)
            s1 = fmaf(mks[r], Wmb[r*HID + t], s1);
        mbsh[t] = s1;   // mbd cancels in softmax; never computed
    }
    {
        int h = t & 31, l0 = t >> 5;
        #pragma unroll
        for (int j = 0; j < 3; j++) {
            int l = l0 + 4*j;
            float p1 = 0.f;
            #pragma unroll
            for (int k = 0; k < HID; k++)
                p1 = fmaf(st[l*HID + k], A1[k*32 + h], p1);
            p1s[l*32 + h] = p1;
        }
    }
    __syncthreads();
    // repack to C-fragment order (lane-major, j*4+i), zero rows 12..15
    if (t < 32) {
        int lane = t, r0 = lane >> 2, cb = 2*(lane & 3);
        float vals[16];
        #pragma unroll
        for (int j = 0; j < 4; j++)
            #pragma unroll
            for (int i = 0; i < 4; i++) {
                int row = r0 + ((i >= 2) ? 8 : 0);
                int col = 8*j + cb + (i & 1);
                vals[j*4 + i] = (row < L1D) ? (p1s[row*32 + col] + mbsh[col]) : 0.f;
            }
        float4* gp = (float4*)&g_P1mc[(size_t)nb*512 + lane*16];
        gp[0] = *(float4*)&vals[0];  gp[1] = *(float4*)&vals[4];
        gp[2] = *(float4*)&vals[8];  gp[3] = *(float4*)&vals[12];
    }
}

// ---------------- L4: k_main — tensor cores; epilogue reuses mma A-fragments ----------------
// per-warp smem (bytes): ssb 2x1024 @0 | A2b 2x2048 @2048 | p1c 2x2048 @6144
// B1/dd tiles borrow A2b[0]/ssb[0] as prologue temps (register fragments afterward).
#define PWB 10240
#define SMEM_MAIN (768 + 4*PWB)   // 41728 bytes -> 5 blocks/SM

__global__ void __launch_bounds__(128, 5) k_main(const int* __restrict__ src,
                                                 const float* __restrict__ W_out,
                                                 const float* __restrict__ b_out,
                                                 float* __restrict__ out) {
    extern __shared__ __align__(16) char sh[];
    int* ekeys = (int*)sh;              // 96 ints
    int* slist = (int*)(sh + 384);      // 96 ints

    int t = threadIdx.x, wid = t >> 5, lane = t & 31;
    int n = blockIdx.x, b = wid;
    int nbd = n*4 + b;
    int es = g_offsets[n];
    int deg = g_offsets[n+1] - es;
    int degc = (deg < MAXDEG) ? deg : MAXDEG;

    if (t < degc) ekeys[t] = g_sorted[es + t];

    char* wb = sh + 768 + wid*PWB;
    __half* ssb = (__half*)wb;                 // 2 x 512 halves (ldmatrix A-layout ss)
    __half* A2b = (__half*)(wb + 2048);        // 2 x 1024 halves
    float*  p1c = (float*)(wb + 6144);         // 2 x 512 floats (C-fragment P1m)
    float*  news = (float*)(wb + 2048);        // alias over A2b after loop

    // prologue: B1 into A2b[0] temp, dd into ssb[0] temp; zero ss pad rows (persist)
    {
        const uint4* pb1 = (const uint4*)&g_B1h[(size_t)nbd*1024];
        #pragma unroll
        for (int i = lane; i < 128; i += 32) ((uint4*)A2b)[i] = pb1[i];
        const uint4* pdd = (const uint4*)&g_sth[(size_t)nbd*384];
        if (lane < 32) ((uint4*)ssb)[lane] = pdd[lane];
        if (lane < 16) ((uint4*)ssb)[32 + lane] = pdd[32 + lane];
        uint4 z = {0,0,0,0};
        if (lane < 16) ((uint4*)ssb)[48 + lane] = z;           // rows 12-15 buf0
        if (lane < 16) ((uint4*)(ssb + 512))[48 + lane] = z;   // rows 12-15 buf1
    }
    __syncwarp();

    // fragment-lane geometry
    int qr = lane & 7, q = lane >> 3;
    u32 offM = (u32)((qr + (q & 1)*8)*64 + (q >> 1)*16);
    int r0 = lane >> 2;
    int cbase = 2*(lane & 3);

    u32 sSS = (u32)__cvta_generic_to_shared(ssb);
    u32 sA2 = (u32)__cvta_generic_to_shared(A2b);
    u32 sP1 = (u32)__cvta_generic_to_shared(p1c);

    // fixed fragments from temps
    u32 b1f[2][4][2];
    #pragma unroll
    for (int s = 0; s < 2; s++)
        #pragma unroll
        for (int p = 0; p < 2; p++) {
            u32 r0_, r1_, r2_, r3_;
            ldsm4t(r0_, r1_, r2_, r3_, sA2 + offM + s*1024 + p*32);
            b1f[s][p*2][0] = r0_;   b1f[s][p*2][1] = r1_;
            b1f[s][p*2+1][0] = r2_; b1f[s][p*2+1][1] = r3_;
        }
    u32 ddf[2][4];
    #pragma unroll
    for (int s = 0; s < 2; s++)
        ldsm4(ddf[s][0], ddf[s][1], ddf[s][2], ddf[s][3], sSS + offM + s*32);

    __syncthreads();
    if (t < degc) {
        int key = ekeys[t], r = 0;
        for (int j = 0; j < degc; j++) r += (ekeys[j] < key);
        slist[r] = src[key];
    }
    __syncthreads();

    float den[4][4], num[4][4];
    #pragma unroll
    for (int j = 0; j < 4; j++)
        #pragma unroll
        for (int i = 0; i < 4; i++) { den[j][i] = 0.f; num[j][i] = 0.f; }

    auto stageEdge = [&](int nbs, int v) {
        const char* pa = (const char*)&g_A2h[(size_t)nbs*1024];
        u32 da = sA2 + v*2048;
        #pragma unroll
        for (int r = 0; r < 4; r++) {
            int c = lane + 32*r;
            cpa16(da + c*16, pa + c*16);
        }
        const char* ps = (const char*)&g_sth[(size_t)nbs*384];   // 768B ldmatrix layout
        u32 dsa = sSS + v*1024;
        cpa16(dsa + lane*16, ps + lane*16);
        if (lane < 16) cpa16(dsa + (32+lane)*16, ps + (32+lane)*16);
        const char* pp = (const char*)&g_P1mc[(size_t)nbs*512];  // 2048B fragment layout
        u32 dp = sP1 + v*2048;
        #pragma unroll
        for (int r = 0; r < 4; r++) {
            int c = lane + 32*r;
            cpa16(dp + c*16, pp + c*16);
        }
    };

    auto computeEdge = [&](int v) {
        u32 ssbase = sSS + v*1024;
        u32 a2base = sA2 + v*2048;
        u32 ssf[2][4];
        #pragma unroll
        for (int s = 0; s < 2; s++)
            ldsm4(ssf[s][0], ssf[s][1], ssf[s][2], ssf[s][3], ssbase + offM + s*32);
        u32 a2f[2][4][2];
        #pragma unroll
        for (int s = 0; s < 2; s++)
            #pragma unroll
            for (int p = 0; p < 2; p++) {
                u32 r0_, r1_, r2_, r3_;
                ldsm4t(r0_, r1_, r2_, r3_, a2base + offM + s*1024 + p*32);
                a2f[s][p*2][0] = r0_;   a2f[s][p*2][1] = r1_;
                a2f[s][p*2+1][0] = r2_; a2f[s][p*2+1][1] = r3_;
            }
        const float4* pf = (const float4*)(p1c + v*512) + lane*4;
        #pragma unroll
        for (int j = 0; j < 4; j++) {
            float c0 = 0.f, c1 = 0.f, c2 = 0.f, c3 = 0.f;
            mma16816(c0, c1, c2, c3, ssf[0][0], ssf[0][1], ssf[0][2], ssf[0][3],
                     b1f[0][j][0], b1f[0][j][1]);
            mma16816(c0, c1, c2, c3, ssf[1][0], ssf[1][1], ssf[1][2], ssf[1][3],
                     b1f[1][j][0], b1f[1][j][1]);
            mma16816(c0, c1, c2, c3, ddf[0][0], ddf[0][1], ddf[0][2], ddf[0][3],
                     a2f[0][j][0], a2f[0][j][1]);
            mma16816(c0, c1, c2, c3, ddf[1][0], ddf[1][1], ddf[1][2], ddf[1][3],
                     a2f[1][j][0], a2f[1][j][1]);
            float4 pj = pf[j];
            // state[src] at C positions == mma A-fragment registers (bit-exact reuse):
            // rows gid/gid+8, cols 8j+2*tig+{0,1}  ->  ssf[j>>1][(j&1)*2 + {0,1}]
            u32 sa_ = ssf[j >> 1][(j & 1)*2];
            u32 sb_ = ssf[j >> 1][(j & 1)*2 + 1];
            float2 fa = __half22float2(*reinterpret_cast<__half2*>(&sa_));
            float2 fb = __half22float2(*reinterpret_cast<__half2*>(&sb_));
            float w0 = __expf(c0 + pj.x);
            float w1 = __expf(c1 + pj.y);
            float w2 = __expf(c2 + pj.z);
            float w3 = __expf(c3 + pj.w);
            den[j][0] += w0; den[j][1] += w1; den[j][2] += w2; den[j][3] += w3;
            num[j][0] = fmaf(w0, fa.x, num[j][0]);
            num[j][1] = fmaf(w1, fa.y, num[j][1]);
            num[j][2] = fmaf(w2, fb.x, num[j][2]);
            num[j][3] = fmaf(w3, fb.y, num[j][3]);
        }
    };

    for (int m = 0; m < degc + 1; m++) {
        if (m < degc) {
            stageEdge(slist[m]*4 + b, m & 1);
            cpcommit();
        }
        if (m > 0) {
            if (m < degc) cpwait<1>(); else cpwait<0>();
            __syncwarp();
            computeEdge((m - 1) & 1);
            __syncwarp();
        }
    }

    // overflow fallback (deg > MAXDEG): synchronous, rare
    for (int i = MAXDEG; i < deg; i++) {
        int nbs = src[g_sorted[es + i]]*4 + b;
        stageEdge(nbs, 0);
        cpcommit();
        cpwait<0>();
        __syncwarp();
        computeEdge(0);
        __syncwarp();
    }
    __syncwarp();

    // finalize softmax into news (aliases A2b; staging dead)
    #pragma unroll
    for (int j = 0; j < 4; j++) {
        int col = 8*j + cbase;
        float d0 = den[j][0], d1 = den[j][1], d2 = den[j][2], d3 = den[j][3];
        float2 lo;
        lo.x = __fdividef(num[j][0], d0 == 0.f ? 1.f : d0);
        lo.y = __fdividef(num[j][1], d1 == 0.f ? 1.f : d1);
        *(float2*)&news[r0*32 + col] = lo;
        if (r0 < 4) {
            float2 hi;
            hi.x = __fdividef(num[j][2], d2 == 0.f ? 1.f : d2);
            hi.y = __fdividef(num[j][3], d3 == 0.f ? 1.f : d3);
            *(float2*)&news[(r0+8)*32 + col] = hi;
        }
    }
    __syncwarp();

    // output projection
    for (int oi = lane; oi < L1D*OUTD; oi += 32) {
        int l = oi >> 4, o = oi & 15;
        float acc = __ldg(&b_out[o]);
        #pragma unroll
        for (int h = 0; h < HID; h++)
            acc = fmaf(news[l*32 + h], __ldg(&W_out[h*16 + o]), acc);
        out[((b*L1D + l)*N_NODES + n)*OUTD + o] = acc;
    }
}

// ---------------- launch ----------------
extern "C" void kernel_launch(void* const* d_in, const int* in_sizes, int n_in,
                              void* d_out, int out_size) {
    const float* long_states = (const float*)d_in[0];
    const float* short_in    = (const float*)d_in[1];
    const int*   src         = (const int*)d_in[2];
    const int*   dst         = (const int*)d_in[3];
    const float* W_in        = (const float*)d_in[4];
    const float* b_in        = (const float*)d_in[5];
    const float* W_metaW     = (const float*)d_in[6];
    const float* b_metaW     = (const float*)d_in[7];
    const float* W_metab     = (const float*)d_in[8];
    const float* b_metab     = (const float*)d_in[9];
    const float* W_out       = (const float*)d_in[10];
    const float* b_out       = (const float*)d_in[11];
    float* out = (float*)d_out;

    cudaFuncSetAttribute(k_main, cudaFuncAttributeMaxDynamicSharedMemorySize, SMEM_MAIN);

    k_statehistmeta<<<N_NODES + 4000, 128>>>(short_in, W_in, b_in, dst,
                                             long_states, W_metaW, b_metaW);
    k_scan<<<1, 1024>>>();
    k_pmbscatter<<<NB, 128>>>(dst, long_states, W_metab, b_metab);
    k_main<<<N_NODES, 128, SMEM_MAIN>>>(src, W_out, b_out, out);
}

// round 14
// speedup vs baseline: 1.1460x; 1.1046x over previous
#include <cuda_runtime.h>
#include <cuda_fp16.h>

#define N_NODES 2000
#define N_EDGES 16000
#define BB 4
#define L1D 12
#define IN_DIM 16
#define REF 32
#define HID 32
#define OUTD 16
#define NB (N_NODES*BB)   // 8000
#define MAXDEG 96

typedef unsigned long long u64;
typedef unsigned int u32;

// ---------------- scratch (device globals; no allocation) ----------------
__device__ __half g_sth[NB*384];     // fp16 state, row-major [nb][l*32+h]
__device__ __half g_A1h[NB*1024];    // A1 fp16 (bias incl)  -> pmb (P1)
__device__ __half g_A2h[NB*1024];    // A2 fp16 (bias incl)  -> k_main, [k][h]
__device__ __half g_B1h[NB*1024];    // B1 fp16              -> k_main, [k][h]
__device__ __half g_P1mh[NB*512];    // (P1 + mbs) fp16, C-fragment order, zero-padded
__device__ int    g_counts[N_NODES]; // zero at load; k_scan re-zeroes each replay
__device__ int    g_cursor[N_NODES];
__device__ int    g_offsets[N_NODES+1];
__device__ int    g_sorted[N_EDGES];

// ---------------- f32x2 packed helpers ----------------
__device__ __forceinline__ u64 pk2(float lo, float hi) {
    u64 r; asm("mov.b64 %0, {%1,%2};" : "=l"(r) : "f"(lo), "f"(hi)); return r;
}
__device__ __forceinline__ u64 pk2s(float v) { return pk2(v, v); }
__device__ __forceinline__ void upk2(float& lo, float& hi, u64 v) {
    asm("mov.b64 {%0,%1}, %2;" : "=f"(lo), "=f"(hi) : "l"(v));
}
__device__ __forceinline__ u64 fma2(u64 a, u64 b, u64 c) {
    u64 d; asm("fma.rn.f32x2 %0, %1, %2, %3;" : "=l"(d) : "l"(a), "l"(b), "l"(c)); return d;
}
__device__ __forceinline__ u64 add2(u64 a, u64 b) {
    u64 d; asm("add.rn.f32x2 %0, %1, %2;" : "=l"(d) : "l"(a), "l"(b)); return d;
}
__device__ __forceinline__ u32 h2u(u64 p) {
    float lo, hi; upk2(lo, hi, p);
    __half2 h = __floats2half2_rn(lo, hi);
    return *reinterpret_cast<u32*>(&h);
}

// ---------------- cp.async / ldmatrix / mma helpers ----------------
__device__ __forceinline__ void cpa16(u32 s, const void* g) {
    asm volatile("cp.async.cg.shared.global [%0], [%1], 16;" :: "r"(s), "l"(g));
}
__device__ __forceinline__ void cpcommit() { asm volatile("cp.async.commit_group;"); }
template<int N> __device__ __forceinline__ void cpwait() {
    asm volatile("cp.async.wait_group %0;" :: "n"(N));
}
__device__ __forceinline__ void ldsm4(u32& r0, u32& r1, u32& r2, u32& r3, u32 addr) {
    asm volatile("ldmatrix.sync.aligned.m8n8.x4.shared.b16 {%0,%1,%2,%3}, [%4];"
        : "=r"(r0), "=r"(r1), "=r"(r2), "=r"(r3) : "r"(addr));
}
__device__ __forceinline__ void ldsm4t(u32& r0, u32& r1, u32& r2, u32& r3, u32 addr) {
    asm volatile("ldmatrix.sync.aligned.m8n8.x4.trans.shared.b16 {%0,%1,%2,%3}, [%4];"
        : "=r"(r0), "=r"(r1), "=r"(r2), "=r"(r3) : "r"(addr));
}
__device__ __forceinline__ void mma16816(float& c0, float& c1, float& c2, float& c3,
                                         u32 a0, u32 a1, u32 a2, u32 a3, u32 b0, u32 b1) {
    asm volatile("mma.sync.aligned.m16n8k16.row.col.f32.f16.f16.f32 "
        "{%0,%1,%2,%3}, {%4,%5,%6,%7}, {%8,%9}, {%0,%1,%2,%3};"
        : "+f"(c0), "+f"(c1), "+f"(c2), "+f"(c3)
        : "r"(a0), "r"(a1), "r"(a2), "r"(a3), "r"(b0), "r"(b1));
}

// ---------------- L1: fused state(+hist) | meta GEMM ----------------
__global__ void __launch_bounds__(128) k_statehistmeta(
        const float* __restrict__ x, const float* __restrict__ W_in,
        const float* __restrict__ b_in, const int* __restrict__ dst,
        const float* __restrict__ mk, const float* __restrict__ W,
        const float* __restrict__ bW) {
    __shared__ __align__(16) float shm[9216];
    int t = threadIdx.x;
    int bx = blockIdx.x;

    if (bx < N_NODES) {
        int n = bx;
        float* xs = shm;
        float* ws = shm + 768;
        float* bs = shm + 1280;
        if (t < 8) atomicAdd(&g_counts[dst[8*n + t]], 1);
        for (int i = t; i < IN_DIM*HID; i += 128) ws[i] = W_in[i];
        if (t < HID) bs[t] = b_in[t];
        for (int i = t; i < BB*L1D*IN_DIM; i += 128) {
            int bl = i / IN_DIM, ii = i % IN_DIM;
            int b = bl / L1D, l = bl % L1D;
            xs[i] = x[((b*L1D + l)*N_NODES + n)*IN_DIM + ii];
        }
        __syncthreads();
        for (int o = t; o < BB*L1D*HID; o += 128) {
            int h = o % HID, bl = o / HID;
            float acc = bs[h];
            #pragma unroll
            for (int i = 0; i < IN_DIM; i++)
                acc = fmaf(xs[bl*IN_DIM + i], ws[i*HID + h], acc);
            g_sth[n*(BB*L1D*HID) + o] = __float2half_rn(acc);
        }
        return;
    }

    int m = bx - N_NODES;
    int nb0 = (m % 250) * 32;
    int c0  = (m / 250) * 128;
    bool needB = (c0 < 1024);       // B2 cancels in softmax -> second half A-only
    float* mks = shm;
    float* wA  = shm + 1024;
    float* wB  = shm + 5120;
    for (int i = t; i < 1024; i += 128) {
        int row = i >> 5, r = i & 31;
        int nb = nb0 + row, n = nb >> 2, b = nb & 3;
        mks[i] = mk[(b*N_NODES + n)*REF + r];
    }
    for (int i = t; i < 1024; i += 128) {
        int r = (i*4) >> 7, c = (i*4) & 127;
        *(float4*)&wA[r*128 + c] = *(const float4*)&W[r*2048 + c0 + c];
        if (needB)
            *(float4*)&wB[r*128 + c] = *(const float4*)&W[(r + REF)*2048 + c0 + c];
    }
    __syncthreads();
    int tc = t & 15, tr = t >> 4;
    int row0 = tr * 4, col0 = tc * 8;
    u64 accA[4][4], accB[4][4];
    #pragma unroll
    for (int i = 0; i < 4; i++)
        #pragma unroll
        for (int j = 0; j < 4; j++) { accA[i][j] = 0ull; accB[i][j] = 0ull; }
    if (needB) {
        #pragma unroll 8
        for (int r = 0; r < REF; r++) {
            ulonglong2 wa0 = *(const ulonglong2*)&wA[r*128 + col0];
            ulonglong2 wa1 = *(const ulonglong2*)&wA[r*128 + col0 + 4];
            ulonglong2 wb0 = *(const ulonglong2*)&wB[r*128 + col0];
            ulonglong2 wb1 = *(const ulonglong2*)&wB[r*128 + col0 + 4];
            #pragma unroll
            for (int i = 0; i < 4; i++) {
                u64 a = pk2s(mks[(row0 + i)*32 + r]);
                accA[i][0] = fma2(a, wa0.x, accA[i][0]);
                accA[i][1] = fma2(a, wa0.y, accA[i][1]);
                accA[i][2] = fma2(a, wa1.x, accA[i][2]);
                accA[i][3] = fma2(a, wa1.y, accA[i][3]);
                accB[i][0] = fma2(a, wb0.x, accB[i][0]);
                accB[i][1] = fma2(a, wb0.y, accB[i][1]);
                accB[i][2] = fma2(a, wb1.x, accB[i][2]);
                accB[i][3] = fma2(a, wb1.y, accB[i][3]);
            }
        }
    } else {
        #pragma unroll 8
        for (int r = 0; r < REF; r++) {
            ulonglong2 wa0 = *(const ulonglong2*)&wA[r*128 + col0];
            ulonglong2 wa1 = *(const ulonglong2*)&wA[r*128 + col0 + 4];
            #pragma unroll
            for (int i = 0; i < 4; i++) {
                u64 a = pk2s(mks[(row0 + i)*32 + r]);
                accA[i][0] = fma2(a, wa0.x, accA[i][0]);
                accA[i][1] = fma2(a, wa0.y, accA[i][1]);
                accA[i][2] = fma2(a, wa1.x, accA[i][2]);
                accA[i][3] = fma2(a, wa1.y, accA[i][3]);
            }
        }
    }
    ulonglong2 bv0 = *(const ulonglong2*)&bW[c0 + col0];
    ulonglong2 bv1 = *(const ulonglong2*)&bW[c0 + col0 + 4];
    #pragma unroll
    for (int i = 0; i < 4; i++) {
        int nb = nb0 + row0 + i;
        u64 oa0 = add2(accA[i][0], bv0.x), oa1 = add2(accA[i][1], bv0.y);
        u64 oa2 = add2(accA[i][2], bv1.x), oa3 = add2(accA[i][3], bv1.y);
        uint4 ha = { h2u(oa0), h2u(oa1), h2u(oa2), h2u(oa3) };
        if (needB) {
            int off = nb*1024 + c0 + col0;
            *(uint4*)&g_A1h[off] = ha;
            uint4 hb = { h2u(accB[i][0]), h2u(accB[i][1]), h2u(accB[i][2]), h2u(accB[i][3]) };
            *(uint4*)&g_B1h[off] = hb;
        } else {
            int off = nb*1024 + (c0 - 1024) + col0;
            *(uint4*)&g_A2h[off] = ha;
        }
    }
}

// ---------------- L2: scan (re-zeroes g_counts for next replay) ----------------
__global__ void k_scan() {
    __shared__ int sb[1024];
    int t = threadIdx.x;
    int i0 = 2*t, i1 = 2*t + 1;
    int a0 = (i0 < N_NODES) ? g_counts[i0] : 0;
    int a1 = (i1 < N_NODES) ? g_counts[i1] : 0;
    sb[t] = a0 + a1;
    __syncthreads();
    for (int off = 1; off < 1024; off <<= 1) {
        int v = (t >= off) ? sb[t - off] : 0;
        __syncthreads();
        sb[t] += v;
        __syncthreads();
    }
    int excl = sb[t] - (a0 + a1);
    if (i0 < N_NODES) { g_offsets[i0] = excl;      g_cursor[i0] = excl;      g_counts[i0] = 0; }
    if (i1 < N_NODES) { g_offsets[i1] = excl + a0; g_cursor[i1] = excl + a0; g_counts[i1] = 0; }
    if (t == 1023) g_offsets[N_NODES] = sb[1023];
}

// ---------------- L3: fused pmb (P1mh fragment repack) + scatter ----------------
__global__ void __launch_bounds__(128) k_pmbscatter(
        const int* __restrict__ dst,
        const float* __restrict__ mk, const float* __restrict__ Wmb,
        const float* __restrict__ bmb) {
    int nb = blockIdx.x, n = nb >> 2, b = nb & 3;
    int t = threadIdx.x;

    if (nb < 500 && t < 32) {
        int e = nb * 32 + t;
        if (e < N_EDGES) {
            int d = dst[e];
            int pos = atomicAdd(&g_cursor[d], 1);
            g_sorted[pos] = e;
        }
    }

    __shared__ float st[384];
    __shared__ float A1[1024];
    __shared__ float p1s[384];
    __shared__ float mks[REF];
    __shared__ float mbsh[HID];
    for (int i = t; i < 192; i += 128) {
        __half2 h = *((const __half2*)&g_sth[nb*384] + i);
        float2 f = __half22float2(h);
        st[2*i] = f.x; st[2*i + 1] = f.y;
    }
    for (int i = t; i < 512; i += 128) {
        __half2 h = *((const __half2*)&g_A1h[(size_t)nb*1024] + i);
        float2 f = __half22float2(h);
        A1[2*i] = f.x; A1[2*i + 1] = f.y;
    }
    if (t < REF) mks[t] = mk[(b*N_NODES + n)*REF + t];
    __syncthreads();
    if (t < HID) {
        float s1 = 0.f;
        #pragma unroll
        for (int r = 0; r < REF; r++)
            s1 = fmaf(mks[r], Wmb[r*HID + t], s1);
        mbsh[t] = s1;   // mbd cancels in softmax; never computed
    }
    {
        int h = t & 31, l0 = t >> 5;
        #pragma unroll
        for (int j = 0; j < 3; j++) {
            int l = l0 + 4*j;
            float p1 = 0.f;
            #pragma unroll
            for (int k = 0; k < HID; k++)
                p1 = fmaf(st[l*HID + k], A1[k*32 + h], p1);
            p1s[l*32 + h] = p1;
        }
    }
    __syncthreads();
    // repack to C-fragment order (lane-major, j*4+i) as fp16, zero rows 12..15
    if (t < 32) {
        int lane = t, r0 = lane >> 2, cb = 2*(lane & 3);
        __half hv[16];
        #pragma unroll
        for (int j = 0; j < 4; j++)
            #pragma unroll
            for (int i = 0; i < 4; i++) {
                int row = r0 + ((i >= 2) ? 8 : 0);
                int col = 8*j + cb + (i & 1);
                float v = (row < L1D) ? (p1s[row*32 + col] + mbsh[col]) : 0.f;
                hv[j*4 + i] = __float2half_rn(v);
            }
        uint4* gp = (uint4*)&g_P1mh[(size_t)nb*512 + lane*16];
        gp[0] = *(uint4*)&hv[0];
        gp[1] = *(uint4*)&hv[8];
    }
}

// ---------------- L4: k_main — tensor cores; P1 via register LDG prefetch ----------------
// per-warp smem (bytes): ssb 2x1024 @0 | A2b 2x2048 @2048
#define PWB 6144
#define SMEM_MAIN (768 + 4*PWB)   // 25344 bytes

__global__ void __launch_bounds__(128, 5) k_main(const int* __restrict__ src,
                                                 const float* __restrict__ W_out,
                                                 const float* __restrict__ b_out,
                                                 float* __restrict__ out) {
    extern __shared__ __align__(16) char sh[];
    int* ekeys = (int*)sh;              // 96 ints
    int* slist = (int*)(sh + 384);      // 96 ints

    int t = threadIdx.x, wid = t >> 5, lane = t & 31;
    int n = blockIdx.x, b = wid;
    int nbd = n*4 + b;
    int es = g_offsets[n];
    int deg = g_offsets[n+1] - es;
    int degc = (deg < MAXDEG) ? deg : MAXDEG;

    if (t < degc) ekeys[t] = g_sorted[es + t];

    char* wb = sh + 768 + wid*PWB;
    __half* ssb = (__half*)wb;                 // 2 x 512 halves (ldmatrix A-layout ss)
    __half* A2b = (__half*)(wb + 2048);        // 2 x 1024 halves
    float*  news = (float*)(wb + 2048);        // alias over A2b after loop

    // prologue: B1 into A2b[0] temp, dd into ssb[0] temp; zero ss pad rows (persist)
    {
        const uint4* pb1 = (const uint4*)&g_B1h[(size_t)nbd*1024];
        #pragma unroll
        for (int i = lane; i < 128; i += 32) ((uint4*)A2b)[i] = pb1[i];
        const uint4* pdd = (const uint4*)&g_sth[(size_t)nbd*384];
        if (lane < 32) ((uint4*)ssb)[lane] = pdd[lane];
        if (lane < 16) ((uint4*)ssb)[32 + lane] = pdd[32 + lane];
        uint4 z = {0,0,0,0};
        if (lane < 16) ((uint4*)ssb)[48 + lane] = z;           // rows 12-15 buf0
        if (lane < 16) ((uint4*)(ssb + 512))[48 + lane] = z;   // rows 12-15 buf1
    }
    __syncwarp();

    // fragment-lane geometry
    int qr = lane & 7, q = lane >> 3;
    u32 offM = (u32)((qr + (q & 1)*8)*64 + (q >> 1)*16);
    int r0 = lane >> 2;
    int cbase = 2*(lane & 3);

    u32 sSS = (u32)__cvta_generic_to_shared(ssb);
    u32 sA2 = (u32)__cvta_generic_to_shared(A2b);

    // fixed fragments from temps
    u32 b1f[2][4][2];
    #pragma unroll
    for (int s = 0; s < 2; s++)
        #pragma unroll
        for (int p = 0; p < 2; p++) {
            u32 r0_, r1_, r2_, r3_;
            ldsm4t(r0_, r1_, r2_, r3_, sA2 + offM + s*1024 + p*32);
            b1f[s][p*2][0] = r0_;   b1f[s][p*2][1] = r1_;
            b1f[s][p*2+1][0] = r2_; b1f[s][p*2+1][1] = r3_;
        }
    u32 ddf[2][4];
    #pragma unroll
    for (int s = 0; s < 2; s++)
        ldsm4(ddf[s][0], ddf[s][1], ddf[s][2], ddf[s][3], sSS + offM + s*32);

    __syncthreads();
    if (t < degc) {
        int key = ekeys[t], r = 0;
        for (int j = 0; j < degc; j++) r += (ekeys[j] < key);
        slist[r] = src[key];
    }
    __syncthreads();

    float den[4][4], num[4][4];
    #pragma unroll
    for (int j = 0; j < 4; j++)
        #pragma unroll
        for (int i = 0; i < 4; i++) { den[j][i] = 0.f; num[j][i] = 0.f; }

    uint4 p1r[2];   // this-edge P1m fragments (fp16), register-prefetched

    auto stageEdge = [&](int nbs, int v) {
        const char* pa = (const char*)&g_A2h[(size_t)nbs*1024];
        u32 da = sA2 + v*2048;
        #pragma unroll
        for (int r = 0; r < 4; r++) {
            int c = lane + 32*r;
            cpa16(da + c*16, pa + c*16);
        }
        const char* ps = (const char*)&g_sth[(size_t)nbs*384];   // 768B ldmatrix layout
        u32 dsa = sSS + v*1024;
        cpa16(dsa + lane*16, ps + lane*16);
        if (lane < 16) cpa16(dsa + (32+lane)*16, ps + (32+lane)*16);
    };

    auto computeEdge = [&](int v) {
        u32 ssbase = sSS + v*1024;
        u32 a2base = sA2 + v*2048;
        u32 ssf[2][4];
        #pragma unroll
        for (int s = 0; s < 2; s++)
            ldsm4(ssf[s][0], ssf[s][1], ssf[s][2], ssf[s][3], ssbase + offM + s*32);
        u32 a2f[2][4][2];
        #pragma unroll
        for (int s = 0; s < 2; s++)
            #pragma unroll
            for (int p = 0; p < 2; p++) {
                u32 r0_, r1_, r2_, r3_;
                ldsm4t(r0_, r1_, r2_, r3_, a2base + offM + s*1024 + p*32);
                a2f[s][p*2][0] = r0_;   a2f[s][p*2][1] = r1_;
                a2f[s][p*2+1][0] = r2_; a2f[s][p*2+1][1] = r3_;
            }
        const __half2* ph = (const __half2*)p1r;   // 8 half2: j*2, j*2+1
        #pragma unroll
        for (int j = 0; j < 4; j++) {
            float c0 = 0.f, c1 = 0.f, c2 = 0.f, c3 = 0.f;
            mma16816(c0, c1, c2, c3, ssf[0][0], ssf[0][1], ssf[0][2], ssf[0][3],
                     b1f[0][j][0], b1f[0][j][1]);
            mma16816(c0, c1, c2, c3, ssf[1][0], ssf[1][1], ssf[1][2], ssf[1][3],
                     b1f[1][j][0], b1f[1][j][1]);
            mma16816(c0, c1, c2, c3, ddf[0][0], ddf[0][1], ddf[0][2], ddf[0][3],
                     a2f[0][j][0], a2f[0][j][1]);
            mma16816(c0, c1, c2, c3, ddf[1][0], ddf[1][1], ddf[1][2], ddf[1][3],
                     a2f[1][j][0], a2f[1][j][1]);
            float2 pa_ = __half22float2(ph[2*j]);
            float2 pb_ = __half22float2(ph[2*j + 1]);
            // state[src] at C positions == mma A-fragment registers (bit-exact reuse)
            u32 sa_ = ssf[j >> 1][(j & 1)*2];
            u32 sb_ = ssf[j >> 1][(j & 1)*2 + 1];
            float2 fa = __half22float2(*reinterpret_cast<__half2*>(&sa_));
            float2 fb = __half22float2(*reinterpret_cast<__half2*>(&sb_));
            float w0 = __expf(c0 + pa_.x);
            float w1 = __expf(c1 + pa_.y);
            float w2 = __expf(c2 + pb_.x);
            float w3 = __expf(c3 + pb_.y);
            den[j][0] += w0; den[j][1] += w1; den[j][2] += w2; den[j][3] += w3;
            num[j][0] = fmaf(w0, fa.x, num[j][0]);
            num[j][1] = fmaf(w1, fa.y, num[j][1]);
            num[j][2] = fmaf(w2, fb.x, num[j][2]);
            num[j][3] = fmaf(w3, fb.y, num[j][3]);
        }
    };

    for (int m = 0; m < degc + 1; m++) {
        if (m < degc) {
            stageEdge(slist[m]*4 + b, m & 1);
            cpcommit();
        }
        if (m > 0) {
            if (m < degc) cpwait<1>(); else cpwait<0>();
            __syncwarp();
            computeEdge((m - 1) & 1);
            __syncwarp();
        }
        if (m < degc) {
            // register-prefetch P1m fragments for edge m (consumed next iteration)
            int nbs = slist[m]*4 + b;
            const uint4* pp = (const uint4*)&g_P1mh[(size_t)nbs*512] + lane*2;
            p1r[0] = __ldg(pp);
            p1r[1] = __ldg(pp + 1);
        }
    }

    // overflow fallback (deg > MAXDEG): synchronous, rare
    for (int i = MAXDEG; i < deg; i++) {
        int nbs = src[g_sorted[es + i]]*4 + b;
        stageEdge(nbs, 0);
        cpcommit();
        cpwait<0>();
        const uint4* pp = (const uint4*)&g_P1mh[(size_t)nbs*512] + lane*2;
        p1r[0] = __ldg(pp);
        p1r[1] = __ldg(pp + 1);
        __syncwarp();
        computeEdge(0);
        __syncwarp();
    }
    __syncwarp();

    // finalize softmax into news (aliases A2b; staging dead)
    #pragma unroll
    for (int j = 0; j < 4; j++) {
        int col = 8*j + cbase;
        float d0 = den[j][0], d1 = den[j][1], d2 = den[j][2], d3 = den[j][3];
        float2 lo;
        lo.x = __fdividef(num[j][0], d0 == 0.f ? 1.f : d0);
        lo.y = __fdividef(num[j][1], d1 == 0.f ? 1.f : d1);
        *(float2*)&news[r0*32 + col] = lo;
        if (r0 < 4) {
            float2 hi;
            hi.x = __fdividef(num[j][2], d2 == 0.f ? 1.f : d2);
            hi.y = __fdividef(num[j][3], d3 == 0.f ? 1.f : d3);
            *(float2*)&news[(r0+8)*32 + col] = hi;
        }
    }
    __syncwarp();

    // output projection
    for (int oi = lane; oi < L1D*OUTD; oi += 32) {
        int l = oi >> 4, o = oi & 15;
        float acc = __ldg(&b_out[o]);
        #pragma unroll
        for (int h = 0; h < HID; h++)
            acc = fmaf(news[l*32 + h], __ldg(&W_out[h*16 + o]), acc);
        out[((b*L1D + l)*N_NODES + n)*OUTD + o] = acc;
    }
}

// ---------------- launch ----------------
extern "C" void kernel_launch(void* const* d_in, const int* in_sizes, int n_in,
                              void* d_out, int out_size) {
    const float* long_states = (const float*)d_in[0];
    const float* short_in    = (const float*)d_in[1];
    const int*   src         = (const int*)d_in[2];
    const int*   dst         = (const int*)d_in[3];
    const float* W_in        = (const float*)d_in[4];
    const float* b_in        = (const float*)d_in[5];
    const float* W_metaW     = (const float*)d_in[6];
    const float* b_metaW     = (const float*)d_in[7];
    const float* W_metab     = (const float*)d_in[8];
    const float* b_metab     = (const float*)d_in[9];
    const float* W_out       = (const float*)d_in[10];
    const float* b_out       = (const float*)d_in[11];
    float* out = (float*)d_out;

    cudaFuncSetAttribute(k_main, cudaFuncAttributeMaxDynamicSharedMemorySize, SMEM_MAIN);

    k_statehistmeta<<<N_NODES + 4000, 128>>>(short_in, W_in, b_in, dst,
                                             long_states, W_metaW, b_metaW);
    k_scan<<<1, 1024>>>();
    k_pmbscatter<<<NB, 128>>>(dst, long_states, W_metab, b_metab);
    k_main<<<N_NODES, 128, SMEM_MAIN>>>(src, W_out, b_out, out);
}

// round 16
// speedup vs baseline: 1.2296x; 1.0730x over previous
#include <cuda_runtime.h>
#include <cuda_fp16.h>

#define N_NODES 2000
#define N_EDGES 16000
#define BB 4
#define L1D 12
#define IN_DIM 16
#define REF 32
#define HID 32
#define OUTD 16
#define NB (N_NODES*BB)   // 8000
#define MAXDEG 96

typedef unsigned long long u64;
typedef unsigned int u32;

// ---------------- scratch (device globals; no allocation) ----------------
__device__ __half g_sth[NB*384];     // fp16 state, row-major [nb][l*32+h]
__device__ __half g_A1h[NB*1024];    // A1 fp16 (bias incl)  -> pmb (P1)
__device__ __half g_A2h[NB*1024];    // A2 fp16 (bias incl)  -> k_main, [k][h]
__device__ __half g_B1h[NB*1024];    // B1 fp16              -> k_main, [k][h]
__device__ __half g_P1mh[NB*512];    // (P1 + mbs) fp16, C-fragment order, zero-padded
__device__ int    g_counts[N_NODES]; // zero at load; k_scan re-zeroes each replay
__device__ int    g_cursor[N_NODES];
__device__ int    g_offsets[N_NODES+1];
__device__ int    g_sorted[N_EDGES];

// ---------------- f32x2 packed helpers ----------------
__device__ __forceinline__ u64 pk2(float lo, float hi) {
    u64 r; asm("mov.b64 %0, {%1,%2};" : "=l"(r) : "f"(lo), "f"(hi)); return r;
}
__device__ __forceinline__ u64 pk2s(float v) { return pk2(v, v); }
__device__ __forceinline__ void upk2(float& lo, float& hi, u64 v) {
    asm("mov.b64 {%0,%1}, %2;" : "=f"(lo), "=f"(hi) : "l"(v));
}
__device__ __forceinline__ u64 fma2(u64 a, u64 b, u64 c) {
    u64 d; asm("fma.rn.f32x2 %0, %1, %2, %3;" : "=l"(d) : "l"(a), "l"(b), "l"(c)); return d;
}
__device__ __forceinline__ u64 add2(u64 a, u64 b) {
    u64 d; asm("add.rn.f32x2 %0, %1, %2;" : "=l"(d) : "l"(a), "l"(b)); return d;
}
__device__ __forceinline__ u32 h2u(u64 p) {
    float lo, hi; upk2(lo, hi, p);
    __half2 h = __floats2half2_rn(lo, hi);
    return *reinterpret_cast<u32*>(&h);
}

// ---------------- cp.async / ldmatrix / mma helpers ----------------
__device__ __forceinline__ void cpa16(u32 s, const void* g) {
    asm volatile("cp.async.cg.shared.global [%0], [%1], 16;" :: "r"(s), "l"(g));
}
__device__ __forceinline__ void cpcommit() { asm volatile("cp.async.commit_group;"); }
template<int N> __device__ __forceinline__ void cpwait() {
    asm volatile("cp.async.wait_group %0;" :: "n"(N));
}
__device__ __forceinline__ void ldsm4(u32& r0, u32& r1, u32& r2, u32& r3, u32 addr) {
    asm volatile("ldmatrix.sync.aligned.m8n8.x4.shared.b16 {%0,%1,%2,%3}, [%4];"
        : "=r"(r0), "=r"(r1), "=r"(r2), "=r"(r3) : "r"(addr));
}
__device__ __forceinline__ void ldsm4t(u32& r0, u32& r1, u32& r2, u32& r3, u32 addr) {
    asm volatile("ldmatrix.sync.aligned.m8n8.x4.trans.shared.b16 {%0,%1,%2,%3}, [%4];"
        : "=r"(r0), "=r"(r1), "=r"(r2), "=r"(r3) : "r"(addr));
}
__device__ __forceinline__ void mma16816(float& c0, float& c1, float& c2, float& c3,
                                         u32 a0, u32 a1, u32 a2, u32 a3, u32 b0, u32 b1) {
    asm volatile("mma.sync.aligned.m16n8k16.row.col.f32.f16.f16.f32 "
        "{%0,%1,%2,%3}, {%4,%5,%6,%7}, {%8,%9}, {%0,%1,%2,%3};"
        : "+f"(c0), "+f"(c1), "+f"(c2), "+f"(c3)
        : "r"(a0), "r"(a1), "r"(a2), "r"(a3), "r"(b0), "r"(b1));
}

// ---------------- L1: fused state(+hist) | meta GEMM ----------------
__global__ void __launch_bounds__(128) k_statehistmeta(
        const float* __restrict__ x, const float* __restrict__ W_in,
        const float* __restrict__ b_in, const int* __restrict__ dst,
        const float* __restrict__ mk, const float* __restrict__ W,
        const float* __restrict__ bW) {
    __shared__ __align__(16) float shm[9216];
    int t = threadIdx.x;
    int bx = blockIdx.x;

    if (bx < N_NODES) {
        int n = bx;
        float* xs = shm;
        float* ws = shm + 768;
        float* bs = shm + 1280;
        if (t < 8) atomicAdd(&g_counts[dst[8*n + t]], 1);
        for (int i = t; i < IN_DIM*HID; i += 128) ws[i] = W_in[i];
        if (t < HID) bs[t] = b_in[t];
        for (int i = t; i < BB*L1D*IN_DIM; i += 128) {
            int bl = i / IN_DIM, ii = i % IN_DIM;
            int b = bl / L1D, l = bl % L1D;
            xs[i] = x[((b*L1D + l)*N_NODES + n)*IN_DIM + ii];
        }
        __syncthreads();
        for (int o = t; o < BB*L1D*HID; o += 128) {
            int h = o % HID, bl = o / HID;
            float acc = bs[h];
            #pragma unroll
            for (int i = 0; i < IN_DIM; i++)
                acc = fmaf(xs[bl*IN_DIM + i], ws[i*HID + h], acc);
            g_sth[n*(BB*L1D*HID) + o] = __float2half_rn(acc);
        }
        return;
    }

    int m = bx - N_NODES;
    int nb0 = (m % 250) * 32;
    int c0  = (m / 250) * 128;
    bool needB = (c0 < 1024);       // B2 cancels in softmax -> second half A-only
    float* mks = shm;
    float* wA  = shm + 1024;
    float* wB  = shm + 5120;
    for (int i = t; i < 1024; i += 128) {
        int row = i >> 5, r = i & 31;
        int nb = nb0 + row, n = nb >> 2, b = nb & 3;
        mks[i] = mk[(b*N_NODES + n)*REF + r];
    }
    for (int i = t; i < 1024; i += 128) {
        int r = (i*4) >> 7, c = (i*4) & 127;
        *(float4*)&wA[r*128 + c] = *(const float4*)&W[r*2048 + c0 + c];
        if (needB)
            *(float4*)&wB[r*128 + c] = *(const float4*)&W[(r + REF)*2048 + c0 + c];
    }
    __syncthreads();
    int tc = t & 15, tr = t >> 4;
    int row0 = tr * 4, col0 = tc * 8;
    u64 accA[4][4], accB[4][4];
    #pragma unroll
    for (int i = 0; i < 4; i++)
        #pragma unroll
        for (int j = 0; j < 4; j++) { accA[i][j] = 0ull; accB[i][j] = 0ull; }
    if (needB) {
        #pragma unroll 8
        for (int r = 0; r < REF; r++) {
            ulonglong2 wa0 = *(const ulonglong2*)&wA[r*128 + col0];
            ulonglong2 wa1 = *(const ulonglong2*)&wA[r*128 + col0 + 4];
            ulonglong2 wb0 = *(const ulonglong2*)&wB[r*128 + col0];
            ulonglong2 wb1 = *(const ulonglong2*)&wB[r*128 + col0 + 4];
            #pragma unroll
            for (int i = 0; i < 4; i++) {
                u64 a = pk2s(mks[(row0 + i)*32 + r]);
                accA[i][0] = fma2(a, wa0.x, accA[i][0]);
                accA[i][1] = fma2(a, wa0.y, accA[i][1]);
                accA[i][2] = fma2(a, wa1.x, accA[i][2]);
                accA[i][3] = fma2(a, wa1.y, accA[i][3]);
                accB[i][0] = fma2(a, wb0.x, accB[i][0]);
                accB[i][1] = fma2(a, wb0.y, accB[i][1]);
                accB[i][2] = fma2(a, wb1.x, accB[i][2]);
                accB[i][3] = fma2(a, wb1.y, accB[i][3]);
            }
        }
    } else {
        #pragma unroll 8
        for (int r = 0; r < REF; r++) {
            ulonglong2 wa0 = *(const ulonglong2*)&wA[r*128 + col0];
            ulonglong2 wa1 = *(const ulonglong2*)&wA[r*128 + col0 + 4];
            #pragma unroll
            for (int i = 0; i < 4; i++) {
                u64 a = pk2s(mks[(row0 + i)*32 + r]);
                accA[i][0] = fma2(a, wa0.x, accA[i][0]);
                accA[i][1] = fma2(a, wa0.y, accA[i][1]);
                accA[i][2] = fma2(a, wa1.x, accA[i][2]);
                accA[i][3] = fma2(a, wa1.y, accA[i][3]);
            }
        }
    }
    ulonglong2 bv0 = *(const ulonglong2*)&bW[c0 + col0];
    ulonglong2 bv1 = *(const ulonglong2*)&bW[c0 + col0 + 4];
    #pragma unroll
    for (int i = 0; i < 4; i++) {
        int nb = nb0 + row0 + i;
        u64 oa0 = add2(accA[i][0], bv0.x), oa1 = add2(accA[i][1], bv0.y);
        u64 oa2 = add2(accA[i][2], bv1.x), oa3 = add2(accA[i][3], bv1.y);
        uint4 ha = { h2u(oa0), h2u(oa1), h2u(oa2), h2u(oa3) };
        if (needB) {
            int off = nb*1024 + c0 + col0;
            *(uint4*)&g_A1h[off] = ha;
            uint4 hb = { h2u(accB[i][0]), h2u(accB[i][1]), h2u(accB[i][2]), h2u(accB[i][3]) };
            *(uint4*)&g_B1h[off] = hb;
        } else {
            int off = nb*1024 + (c0 - 1024) + col0;
            *(uint4*)&g_A2h[off] = ha;
        }
    }
}

// ---------------- L2: scan (re-zeroes g_counts for next replay) ----------------
__global__ void k_scan() {
    __shared__ int sb[1024];
    int t = threadIdx.x;
    int i0 = 2*t, i1 = 2*t + 1;
    int a0 = (i0 < N_NODES) ? g_counts[i0] : 0;
    int a1 = (i1 < N_NODES) ? g_counts[i1] : 0;
    sb[t] = a0 + a1;
    __syncthreads();
    for (int off = 1; off < 1024; off <<= 1) {
        int v = (t >= off) ? sb[t - off] : 0;
        __syncthreads();
        sb[t] += v;
        __syncthreads();
    }
    int excl = sb[t] - (a0 + a1);
    if (i0 < N_NODES) { g_offsets[i0] = excl;      g_cursor[i0] = excl;      g_counts[i0] = 0; }
    if (i1 < N_NODES) { g_offsets[i1] = excl + a0; g_cursor[i1] = excl + a0; g_counts[i1] = 0; }
    if (t == 1023) g_offsets[N_NODES] = sb[1023];
}

// ---------------- L3: pmb via tensor cores (C-fragment direct) + scatter ----------------
// grid 2000 x 128: block n; warp w handles nb = n*4 + w.
__global__ void __launch_bounds__(128) k_pmbscatter(
        const int* __restrict__ dst,
        const float* __restrict__ mk, const float* __restrict__ Wmb,
        const float* __restrict__ bmb) {
    __shared__ __align__(16) __half A1s[4][1024];   // [warp][k*32+h]
    __shared__ __align__(16) __half sts[4][512];    // [warp][l*32+h], rows 12-15 zero
    __shared__ float mbss[128];                      // [warp*32 + h]
    int t = threadIdx.x, wid = t >> 5, lane = t & 31;
    int n = blockIdx.x, b = wid;
    int nb = n*4 + wid;

    if (n < 500 && t < 32) {
        int e = n * 32 + t;
        if (e < N_EDGES) {
            int d = dst[e];
            int pos = atomicAdd(&g_cursor[d], 1);
            g_sorted[pos] = e;
        }
    }

    // per-warp tile loads
    {
        const uint4* pa = (const uint4*)&g_A1h[(size_t)nb*1024];
        uint4* sa = (uint4*)A1s[wid];
        #pragma unroll
        for (int r = 0; r < 4; r++) sa[lane + 32*r] = pa[lane + 32*r];
        const uint4* ps = (const uint4*)&g_sth[(size_t)nb*384];
        uint4* ss = (uint4*)sts[wid];
        ss[lane] = ps[lane];
        if (lane < 16) ss[32 + lane] = ps[32 + lane];
        uint4 z = {0,0,0,0};
        if (lane < 16) ss[48 + lane] = z;
    }
    // mbs[nb][h=lane]  (mbd + bias cancel in softmax)
    {
        float s1 = 0.f;
        const float* mkp = &mk[(b*N_NODES + n)*REF];
        #pragma unroll
        for (int r = 0; r < REF; r++)
            s1 = fmaf(__ldg(&mkp[r]), __ldg(&Wmb[r*HID + lane]), s1);
        mbss[t] = s1;
    }
    __syncwarp();

    // fragment geometry (identical to k_main)
    int qr = lane & 7, q = lane >> 3;
    u32 offM = (u32)((qr + (q & 1)*8)*64 + (q >> 1)*16);
    int r0 = lane >> 2, cbase = 2*(lane & 3);
    u32 sA1 = (u32)__cvta_generic_to_shared(A1s[wid]);
    u32 sSt = (u32)__cvta_generic_to_shared(sts[wid]);

    u32 a1f[2][4][2];
    #pragma unroll
    for (int s = 0; s < 2; s++)
        #pragma unroll
        for (int p = 0; p < 2; p++) {
            u32 r0_, r1_, r2_, r3_;
            ldsm4t(r0_, r1_, r2_, r3_, sA1 + offM + s*1024 + p*32);
            a1f[s][p*2][0] = r0_;   a1f[s][p*2][1] = r1_;
            a1f[s][p*2+1][0] = r2_; a1f[s][p*2+1][1] = r3_;
        }
    u32 stf[2][4];
    #pragma unroll
    for (int s = 0; s < 2; s++)
        ldsm4(stf[s][0], stf[s][1], stf[s][2], stf[s][3], sSt + offM + s*32);

    __half hv[16];
    #pragma unroll
    for (int j = 0; j < 4; j++) {
        float c0 = 0.f, c1 = 0.f, c2 = 0.f, c3 = 0.f;
        mma16816(c0, c1, c2, c3, stf[0][0], stf[0][1], stf[0][2], stf[0][3],
                 a1f[0][j][0], a1f[0][j][1]);
        mma16816(c0, c1, c2, c3, stf[1][0], stf[1][1], stf[1][2], stf[1][3],
                 a1f[1][j][0], a1f[1][j][1]);
        int col = 8*j + cbase;
        float m0 = mbss[wid*32 + col];
        float m1 = mbss[wid*32 + col + 1];
        hv[4*j + 0] = __float2half_rn(c0 + m0);
        hv[4*j + 1] = __float2half_rn(c1 + m1);
        // rows r0+8 valid only when r0 < 4 (pad rows must stay exactly 0)
        hv[4*j + 2] = (r0 < 4) ? __float2half_rn(c2 + m0) : __half(0.f);
        hv[4*j + 3] = (r0 < 4) ? __float2half_rn(c3 + m1) : __half(0.f);
    }
    uint4* gp = (uint4*)&g_P1mh[(size_t)nb*512 + lane*16];
    gp[0] = *(uint4*)&hv[0];
    gp[1] = *(uint4*)&hv[8];
}

// ---------------- L4: k_main — tensor cores; P1 via register LDG prefetch ----------------
// per-warp smem (bytes): ssb 2x1024 @0 | A2b 2x2048 @2048
#define PWB 6144
#define SMEM_MAIN (768 + 4*PWB)   // 25344 bytes

__global__ void __launch_bounds__(128, 5) k_main(const int* __restrict__ src,
                                                 const float* __restrict__ W_out,
                                                 const float* __restrict__ b_out,
                                                 float* __restrict__ out) {
    extern __shared__ __align__(16) char sh[];
    int* ekeys = (int*)sh;              // 96 ints
    int* slist = (int*)(sh + 384);      // 96 ints

    int t = threadIdx.x, wid = t >> 5, lane = t & 31;
    int n = blockIdx.x, b = wid;
    int nbd = n*4 + b;
    int es = g_offsets[n];
    int deg = g_offsets[n+1] - es;
    int degc = (deg < MAXDEG) ? deg : MAXDEG;

    if (t < degc) ekeys[t] = g_sorted[es + t];

    char* wb = sh + 768 + wid*PWB;
    __half* ssb = (__half*)wb;                 // 2 x 512 halves (ldmatrix A-layout ss)
    __half* A2b = (__half*)(wb + 2048);        // 2 x 1024 halves
    float*  news = (float*)(wb + 2048);        // alias over A2b after loop

    // prologue: B1 into A2b[0] temp, dd into ssb[0] temp; zero ss pad rows (persist)
    {
        const uint4* pb1 = (const uint4*)&g_B1h[(size_t)nbd*1024];
        #pragma unroll
        for (int i = lane; i < 128; i += 32) ((uint4*)A2b)[i] = pb1[i];
        const uint4* pdd = (const uint4*)&g_sth[(size_t)nbd*384];
        if (lane < 32) ((uint4*)ssb)[lane] = pdd[lane];
        if (lane < 16) ((uint4*)ssb)[32 + lane] = pdd[32 + lane];
        uint4 z = {0,0,0,0};
        if (lane < 16) ((uint4*)ssb)[48 + lane] = z;           // rows 12-15 buf0
        if (lane < 16) ((uint4*)(ssb + 512))[48 + lane] = z;   // rows 12-15 buf1
    }
    __syncwarp();

    // fragment-lane geometry
    int qr = lane & 7, q = lane >> 3;
    u32 offM = (u32)((qr + (q & 1)*8)*64 + (q >> 1)*16);
    int r0 = lane >> 2;
    int cbase = 2*(lane & 3);

    u32 sSS = (u32)__cvta_generic_to_shared(ssb);
    u32 sA2 = (u32)__cvta_generic_to_shared(A2b);

    // fixed fragments from temps
    u32 b1f[2][4][2];
    #pragma unroll
    for (int s = 0; s < 2; s++)
        #pragma unroll
        for (int p = 0; p < 2; p++) {
            u32 r0_, r1_, r2_, r3_;
            ldsm4t(r0_, r1_, r2_, r3_, sA2 + offM + s*1024 + p*32);
            b1f[s][p*2][0] = r0_;   b1f[s][p*2][1] = r1_;
            b1f[s][p*2+1][0] = r2_; b1f[s][p*2+1][1] = r3_;
        }
    u32 ddf[2][4];
    #pragma unroll
    for (int s = 0; s < 2; s++)
        ldsm4(ddf[s][0], ddf[s][1], ddf[s][2], ddf[s][3], sSS + offM + s*32);

    __syncthreads();
    if (t < degc) {
        int key = ekeys[t], r = 0;
        for (int j = 0; j < degc; j++) r += (ekeys[j] < key);
        slist[r] = src[key];
    }
    __syncthreads();

    float den[4][4], num[4][4];
    #pragma unroll
    for (int j = 0; j < 4; j++)
        #pragma unroll
        for (int i = 0; i < 4; i++) { den[j][i] = 0.f; num[j][i] = 0.f; }

    uint4 p1r[2];   // this-edge P1m fragments (fp16), register-prefetched

    auto stageEdge = [&](int nbs, int v) {
        const char* pa = (const char*)&g_A2h[(size_t)nbs*1024];
        u32 da = sA2 + v*2048;
        #pragma unroll
        for (int r = 0; r < 4; r++) {
            int c = lane + 32*r;
            cpa16(da + c*16, pa + c*16);
        }
        const char* ps = (const char*)&g_sth[(size_t)nbs*384];   // 768B ldmatrix layout
        u32 dsa = sSS + v*1024;
        cpa16(dsa + lane*16, ps + lane*16);
        if (lane < 16) cpa16(dsa + (32+lane)*16, ps + (32+lane)*16);
    };

    auto computeEdge = [&](int v) {
        u32 ssbase = sSS + v*1024;
        u32 a2base = sA2 + v*2048;
        u32 ssf[2][4];
        #pragma unroll
        for (int s = 0; s < 2; s++)
            ldsm4(ssf[s][0], ssf[s][1], ssf[s][2], ssf[s][3], ssbase + offM + s*32);
        u32 a2f[2][4][2];
        #pragma unroll
        for (int s = 0; s < 2; s++)
            #pragma unroll
            for (int p = 0; p < 2; p++) {
                u32 r0_, r1_, r2_, r3_;
                ldsm4t(r0_, r1_, r2_, r3_, a2base + offM + s*1024 + p*32);
                a2f[s][p*2][0] = r0_;   a2f[s][p*2][1] = r1_;
                a2f[s][p*2+1][0] = r2_; a2f[s][p*2+1][1] = r3_;
            }
        const __half2* ph = (const __half2*)p1r;   // 8 half2: j*2, j*2+1
        #pragma unroll
        for (int j = 0; j < 4; j++) {
            float c0 = 0.f, c1 = 0.f, c2 = 0.f, c3 = 0.f;
            mma16816(c0, c1, c2, c3, ssf[0][0], ssf[0][1], ssf[0][2], ssf[0][3],
                     b1f[0][j][0], b1f[0][j][1]);
            mma16816(c0, c1, c2, c3, ssf[1][0], ssf[1][1], ssf[1][2], ssf[1][3],
                     b1f[1][j][0], b1f[1][j][1]);
            mma16816(c0, c1, c2, c3, ddf[0][0], ddf[0][1], ddf[0][2], ddf[0][3],
                     a2f[0][j][0], a2f[0][j][1]);
            mma16816(c0, c1, c2, c3, ddf[1][0], ddf[1][1], ddf[1][2], ddf[1][3],
                     a2f[1][j][0], a2f[1][j][1]);
            float2 pa_ = __half22float2(ph[2*j]);
            float2 pb_ = __half22float2(ph[2*j + 1]);
            // state[src] at C positions == mma A-fragment registers (bit-exact reuse)
            u32 sa_ = ssf[j >> 1][(j & 1)*2];
            u32 sb_ = ssf[j >> 1][(j & 1)*2 + 1];
            float2 fa = __half22float2(*reinterpret_cast<__half2*>(&sa_));
            float2 fb = __half22float2(*reinterpret_cast<__half2*>(&sb_));
            float w0 = __expf(c0 + pa_.x);
            float w1 = __expf(c1 + pa_.y);
            float w2 = __expf(c2 + pb_.x);
            float w3 = __expf(c3 + pb_.y);
            den[j][0] += w0; den[j][1] += w1; den[j][2] += w2; den[j][3] += w3;
            num[j][0] = fmaf(w0, fa.x, num[j][0]);
            num[j][1] = fmaf(w1, fa.y, num[j][1]);
            num[j][2] = fmaf(w2, fb.x, num[j][2]);
            num[j][3] = fmaf(w3, fb.y, num[j][3]);
        }
    };

    for (int m = 0; m < degc + 1; m++) {
        if (m < degc) {
            stageEdge(slist[m]*4 + b, m & 1);
            cpcommit();
        }
        if (m > 0) {
            if (m < degc) cpwait<1>(); else cpwait<0>();
            __syncwarp();
            computeEdge((m - 1) & 1);
            __syncwarp();
        }
        if (m < degc) {
            // register-prefetch P1m fragments for edge m (consumed next iteration)
            int nbs = slist[m]*4 + b;
            const uint4* pp = (const uint4*)&g_P1mh[(size_t)nbs*512] + lane*2;
            p1r[0] = __ldg(pp);
            p1r[1] = __ldg(pp + 1);
        }
    }

    // overflow fallback (deg > MAXDEG): synchronous, rare
    for (int i = MAXDEG; i < deg; i++) {
        int nbs = src[g_sorted[es + i]]*4 + b;
        stageEdge(nbs, 0);
        cpcommit();
        cpwait<0>();
        const uint4* pp = (const uint4*)&g_P1mh[(size_t)nbs*512] + lane*2;
        p1r[0] = __ldg(pp);
        p1r[1] = __ldg(pp + 1);
        __syncwarp();
        computeEdge(0);
        __syncwarp();
    }
    __syncwarp();

    // finalize softmax into news (aliases A2b; staging dead)
    #pragma unroll
    for (int j = 0; j < 4; j++) {
        int col = 8*j + cbase;
        float d0 = den[j][0], d1 = den[j][1], d2 = den[j][2], d3 = den[j][3];
        float2 lo;
        lo.x = __fdividef(num[j][0], d0 == 0.f ? 1.f : d0);
        lo.y = __fdividef(num[j][1], d1 == 0.f ? 1.f : d1);
        *(float2*)&news[r0*32 + col] = lo;
        if (r0 < 4) {
            float2 hi;
            hi.x = __fdividef(num[j][2], d2 == 0.f ? 1.f : d2);
            hi.y = __fdividef(num[j][3], d3 == 0.f ? 1.f : d3);
            *(float2*)&news[(r0+8)*32 + col] = hi;
        }
    }
    __syncwarp();

    // output projection
    for (int oi = lane; oi < L1D*OUTD; oi += 32) {
        int l = oi >> 4, o = oi & 15;
        float acc = __ldg(&b_out[o]);
        #pragma unroll
        for (int h = 0; h < HID; h++)
            acc = fmaf(news[l*32 + h], __ldg(&W_out[h*16 + o]), acc);
        out[((b*L1D + l)*N_NODES + n)*OUTD + o] = acc;
    }
}

// ---------------- launch ----------------
extern "C" void kernel_launch(void* const* d_in, const int* in_sizes, int n_in,
                              void* d_out, int out_size) {
    const float* long_states = (const float*)d_in[0];
    const float* short_in    = (const float*)d_in[1];
    const int*   src         = (const int*)d_in[2];
    const int*   dst         = (const int*)d_in[3];
    const float* W_in        = (const float*)d_in[4];
    const float* b_in        = (const float*)d_in[5];
    const float* W_metaW     = (const float*)d_in[6];
    const float* b_metaW     = (const float*)d_in[7];
    const float* W_metab     = (const float*)d_in[8];
    const float* b_metab     = (const float*)d_in[9];
    const float* W_out       = (const float*)d_in[10];
    const float* b_out       = (const float*)d_in[11];
    float* out = (float*)d_out;

    cudaFuncSetAttribute(k_main, cudaFuncAttributeMaxDynamicSharedMemorySize, SMEM_MAIN);

    k_statehistmeta<<<N_NODES + 4000, 128>>>(short_in, W_in, b_in, dst,
                                             long_states, W_metaW, b_metaW);
    k_scan<<<1, 1024>>>();
    k_pmbscatter<<<N_NODES, 128>>>(dst, long_states, W_metab, b_metab);
    k_main<<<N_NODES, 128, SMEM_MAIN>>>(src, W_out, b_out, out);
}

// round 17
// speedup vs baseline: 1.5623x; 1.2705x over previous
#include <cuda_runtime.h>
#include <cuda_fp16.h>

#define N_NODES 2000
#define N_EDGES 16000
#define BB 4
#define L1D 12
#define IN_DIM 16
#define REF 32
#define HID 32
#define OUTD 16
#define NB (N_NODES*BB)   // 8000
#define MAXDEG 96

typedef unsigned long long u64;
typedef unsigned int u32;

// ---------------- scratch (device globals; no allocation) ----------------
__device__ __half g_sth[NB*384];     // fp16 state, row-major [nb][l*32+h]
__device__ __half g_A1h[NB*1024];    // A1 fp16 (bias incl)  -> pmb (P1)
__device__ __half g_A2h[NB*1024];    // A2 fp16 (bias incl)  -> k_main, [k][h]
__device__ __half g_B1h[NB*1024];    // B1 fp16              -> k_main, [k][h]
__device__ __half g_P1mh[NB*512];    // (P1 + mbs) fp16, C-fragment order, zero-padded
__device__ int    g_counts[N_NODES]; // zero at load; k_scan re-zeroes each replay
__device__ int    g_cursor[N_NODES];
__device__ int    g_offsets[N_NODES+1];
__device__ int    g_sorted[N_EDGES];

// ---------------- cp.async / ldmatrix / mma helpers ----------------
__device__ __forceinline__ void cpa16(u32 s, const void* g) {
    asm volatile("cp.async.cg.shared.global [%0], [%1], 16;" :: "r"(s), "l"(g));
}
__device__ __forceinline__ void cpcommit() { asm volatile("cp.async.commit_group;"); }
template<int N> __device__ __forceinline__ void cpwait() {
    asm volatile("cp.async.wait_group %0;" :: "n"(N));
}
__device__ __forceinline__ void ldsm4(u32& r0, u32& r1, u32& r2, u32& r3, u32 addr) {
    asm volatile("ldmatrix.sync.aligned.m8n8.x4.shared.b16 {%0,%1,%2,%3}, [%4];"
        : "=r"(r0), "=r"(r1), "=r"(r2), "=r"(r3) : "r"(addr));
}
__device__ __forceinline__ void ldsm4t(u32& r0, u32& r1, u32& r2, u32& r3, u32 addr) {
    asm volatile("ldmatrix.sync.aligned.m8n8.x4.trans.shared.b16 {%0,%1,%2,%3}, [%4];"
        : "=r"(r0), "=r"(r1), "=r"(r2), "=r"(r3) : "r"(addr));
}
__device__ __forceinline__ void mma16816(float& c0, float& c1, float& c2, float& c3,
                                         u32 a0, u32 a1, u32 a2, u32 a3, u32 b0, u32 b1) {
    asm volatile("mma.sync.aligned.m16n8k16.row.col.f32.f16.f16.f32 "
        "{%0,%1,%2,%3}, {%4,%5,%6,%7}, {%8,%9}, {%0,%1,%2,%3};"
        : "+f"(c0), "+f"(c1), "+f"(c2), "+f"(c3)
        : "r"(a0), "r"(a1), "r"(a2), "r"(a3), "r"(b0), "r"(b1));
}

// ---------------- L1: fused state(+hist) | meta GEMM (tensor-core) ----------------
// grid 6000 x 128: blocks [0,2000) state+hist; [2000,6000) meta tiles (32nb x 128c)
__global__ void __launch_bounds__(128) k_statehistmeta(
        const float* __restrict__ x, const float* __restrict__ W_in,
        const float* __restrict__ b_in, const int* __restrict__ dst,
        const float* __restrict__ mk, const float* __restrict__ W,
        const float* __restrict__ bW) {
    __shared__ __align__(16) char shmem[18944];
    int t = threadIdx.x;
    int bx = blockIdx.x;

    if (bx < N_NODES) {
        int n = bx;
        float* xs = (float*)shmem;          // 768
        float* ws = (float*)shmem + 768;    // 512
        float* bs = (float*)shmem + 1280;   // 32
        if (t < 8) atomicAdd(&g_counts[dst[8*n + t]], 1);
        for (int i = t; i < IN_DIM*HID; i += 128) ws[i] = W_in[i];
        if (t < HID) bs[t] = b_in[t];
        for (int i = t; i < BB*L1D*IN_DIM; i += 128) {
            int bl = i / IN_DIM, ii = i % IN_DIM;
            int b = bl / L1D, l = bl % L1D;
            xs[i] = x[((b*L1D + l)*N_NODES + n)*IN_DIM + ii];
        }
        __syncthreads();
        for (int o = t; o < BB*L1D*HID; o += 128) {
            int h = o % HID, bl = o / HID;
            float acc = bs[h];
            #pragma unroll
            for (int i = 0; i < IN_DIM; i++)
                acc = fmaf(xs[bl*IN_DIM + i], ws[i*HID + h], acc);
            g_sth[n*(BB*L1D*HID) + o] = __float2half_rn(acc);
        }
        return;
    }

    // ---- meta GEMM tile via tensor cores ----
    int m = bx - N_NODES;
    int nb0 = (m % 250) * 32;
    int c0  = (m / 250) * 128;
    bool needB = (c0 < 1024);       // B2 cancels in softmax -> second half A-only
    __half* mk16 = (__half*)shmem;            // [32 rows][32 k], 64B rows
    __half* W16A = (__half*)(shmem + 2048);   // [32 k][128 c], 256B rows
    __half* W16B = (__half*)(shmem + 10240);  // same, W rows 32-63 (needB only)

    for (int i = t; i < 1024; i += 128) {
        int row = i >> 5, r = i & 31;
        int nb = nb0 + row, n = nb >> 2, b = nb & 3;
        mk16[i] = __float2half_rn(mk[(b*N_NODES + n)*REF + r]);
    }
    for (int i = t; i < 1024; i += 128) {
        int r = i >> 5, c = (i & 31) * 4;
        float4 wa = *(const float4*)&W[r*2048 + c0 + c];
        *(__half2*)&W16A[r*128 + c]     = __floats2half2_rn(wa.x, wa.y);
        *(__half2*)&W16A[r*128 + c + 2] = __floats2half2_rn(wa.z, wa.w);
        if (needB) {
            float4 wb = *(const float4*)&W[(r + REF)*2048 + c0 + c];
            *(__half2*)&W16B[r*128 + c]     = __floats2half2_rn(wb.x, wb.y);
            *(__half2*)&W16B[r*128 + c + 2] = __floats2half2_rn(wb.z, wb.w);
        }
    }
    __syncthreads();

    int wid = t >> 5, lane = t & 31;
    int c0w = wid * 32;
    int qr = lane & 7, q = lane >> 3;
    u32 offA = (u32)((qr + (q & 1)*8)*64  + (q >> 1)*16);    // mk16 (64B stride)
    u32 offW = (u32)((qr + (q & 1)*8)*256 + (q >> 1)*16);    // W16 (256B stride)
    int r0 = lane >> 2, tig = lane & 3;

    u32 sMK = (u32)__cvta_generic_to_shared(mk16);
    u32 sWA = (u32)__cvta_generic_to_shared(W16A);
    u32 sWB = (u32)__cvta_generic_to_shared(W16B);

    // mk A-fragments [rowtile s][ktile kt]
    u32 mkf[2][2][4];
    #pragma unroll
    for (int s = 0; s < 2; s++)
        #pragma unroll
        for (int kt = 0; kt < 2; kt++)
            ldsm4(mkf[s][kt][0], mkf[s][kt][1], mkf[s][kt][2], mkf[s][kt][3],
                  sMK + offA + s*1024 + kt*32);

    // W A-half B-fragments [kt][j]
    u32 wf[2][4][2];
    #pragma unroll
    for (int kt = 0; kt < 2; kt++)
        #pragma unroll
        for (int p = 0; p < 2; p++) {
            u32 r0_, r1_, r2_, r3_;
            ldsm4t(r0_, r1_, r2_, r3_, sWA + offW + kt*4096 + c0w*2 + p*32);
            wf[kt][p*2][0] = r0_;   wf[kt][p*2][1] = r1_;
            wf[kt][p*2+1][0] = r2_; wf[kt][p*2+1][1] = r3_;
        }

    __half* dstA = needB ? g_A1h : g_A2h;
    int cb2 = needB ? c0 : (c0 - 1024);
    #pragma unroll
    for (int s = 0; s < 2; s++)
        #pragma unroll
        for (int j = 0; j < 4; j++) {
            float d0 = 0.f, d1 = 0.f, d2 = 0.f, d3 = 0.f;
            mma16816(d0, d1, d2, d3, mkf[s][0][0], mkf[s][0][1], mkf[s][0][2], mkf[s][0][3],
                     wf[0][j][0], wf[0][j][1]);
            mma16816(d0, d1, d2, d3, mkf[s][1][0], mkf[s][1][1], mkf[s][1][2], mkf[s][1][3],
                     wf[1][j][0], wf[1][j][1]);
            int col = c0w + 8*j + 2*tig;
            float b0 = __ldg(&bW[c0 + col]);
            float b1 = __ldg(&bW[c0 + col + 1]);
            int nbr = nb0 + s*16 + r0;
            *(__half2*)&dstA[(size_t)nbr*1024 + cb2 + col] = __floats2half2_rn(d0 + b0, d1 + b1);
            *(__half2*)&dstA[(size_t)(nbr+8)*1024 + cb2 + col] = __floats2half2_rn(d2 + b0, d3 + b1);
        }

    if (needB) {
        #pragma unroll
        for (int kt = 0; kt < 2; kt++)
            #pragma unroll
            for (int p = 0; p < 2; p++) {
                u32 r0_, r1_, r2_, r3_;
                ldsm4t(r0_, r1_, r2_, r3_, sWB + offW + kt*4096 + c0w*2 + p*32);
                wf[kt][p*2][0] = r0_;   wf[kt][p*2][1] = r1_;
                wf[kt][p*2+1][0] = r2_; wf[kt][p*2+1][1] = r3_;
            }
        #pragma unroll
        for (int s = 0; s < 2; s++)
            #pragma unroll
            for (int j = 0; j < 4; j++) {
                float d0 = 0.f, d1 = 0.f, d2 = 0.f, d3 = 0.f;
                mma16816(d0, d1, d2, d3, mkf[s][0][0], mkf[s][0][1], mkf[s][0][2], mkf[s][0][3],
                         wf[0][j][0], wf[0][j][1]);
                mma16816(d0, d1, d2, d3, mkf[s][1][0], mkf[s][1][1], mkf[s][1][2], mkf[s][1][3],
                         wf[1][j][0], wf[1][j][1]);
                int col = c0w + 8*j + 2*tig;
                int nbr = nb0 + s*16 + r0;
                *(__half2*)&g_B1h[(size_t)nbr*1024 + c0 + col] = __floats2half2_rn(d0, d1);
                *(__half2*)&g_B1h[(size_t)(nbr+8)*1024 + c0 + col] = __floats2half2_rn(d2, d3);
            }
    }
}

// ---------------- L2: scan (re-zeroes g_counts for next replay) ----------------
__global__ void k_scan() {
    __shared__ int sb[1024];
    int t = threadIdx.x;
    int i0 = 2*t, i1 = 2*t + 1;
    int a0 = (i0 < N_NODES) ? g_counts[i0] : 0;
    int a1 = (i1 < N_NODES) ? g_counts[i1] : 0;
    sb[t] = a0 + a1;
    __syncthreads();
    for (int off = 1; off < 1024; off <<= 1) {
        int v = (t >= off) ? sb[t - off] : 0;
        __syncthreads();
        sb[t] += v;
        __syncthreads();
    }
    int excl = sb[t] - (a0 + a1);
    if (i0 < N_NODES) { g_offsets[i0] = excl;      g_cursor[i0] = excl;      g_counts[i0] = 0; }
    if (i1 < N_NODES) { g_offsets[i1] = excl + a0; g_cursor[i1] = excl + a0; g_counts[i1] = 0; }
    if (t == 1023) g_offsets[N_NODES] = sb[1023];
}

// ---------------- L3: pmb via tensor cores (C-fragment direct) + scatter ----------------
__global__ void __launch_bounds__(128) k_pmbscatter(
        const int* __restrict__ dst,
        const float* __restrict__ mk, const float* __restrict__ Wmb,
        const float* __restrict__ bmb) {
    __shared__ __align__(16) __half A1s[4][1024];   // [warp][k*32+h]
    __shared__ __align__(16) __half sts[4][512];    // [warp][l*32+h], rows 12-15 zero
    __shared__ float mbss[128];                      // [warp*32 + h]
    int t = threadIdx.x, wid = t >> 5, lane = t & 31;
    int n = blockIdx.x, b = wid;
    int nb = n*4 + wid;

    if (n < 500 && t < 32) {
        int e = n * 32 + t;
        if (e < N_EDGES) {
            int d = dst[e];
            int pos = atomicAdd(&g_cursor[d], 1);
            g_sorted[pos] = e;
        }
    }

    {
        const uint4* pa = (const uint4*)&g_A1h[(size_t)nb*1024];
        uint4* sa = (uint4*)A1s[wid];
        #pragma unroll
        for (int r = 0; r < 4; r++) sa[lane + 32*r] = pa[lane + 32*r];
        const uint4* ps = (const uint4*)&g_sth[(size_t)nb*384];
        uint4* ss = (uint4*)sts[wid];
        ss[lane] = ps[lane];
        if (lane < 16) ss[32 + lane] = ps[32 + lane];
        uint4 z = {0,0,0,0};
        if (lane < 16) ss[48 + lane] = z;
    }
    {
        float s1 = 0.f;
        const float* mkp = &mk[(b*N_NODES + n)*REF];
        #pragma unroll
        for (int r = 0; r < REF; r++)
            s1 = fmaf(__ldg(&mkp[r]), __ldg(&Wmb[r*HID + lane]), s1);
        mbss[t] = s1;
    }
    __syncwarp();

    int qr = lane & 7, q = lane >> 3;
    u32 offM = (u32)((qr + (q & 1)*8)*64 + (q >> 1)*16);
    int r0 = lane >> 2, cbase = 2*(lane & 3);
    u32 sA1 = (u32)__cvta_generic_to_shared(A1s[wid]);
    u32 sSt = (u32)__cvta_generic_to_shared(sts[wid]);

    u32 a1f[2][4][2];
    #pragma unroll
    for (int s = 0; s < 2; s++)
        #pragma unroll
        for (int p = 0; p < 2; p++) {
            u32 r0_, r1_, r2_, r3_;
            ldsm4t(r0_, r1_, r2_, r3_, sA1 + offM + s*1024 + p*32);
            a1f[s][p*2][0] = r0_;   a1f[s][p*2][1] = r1_;
            a1f[s][p*2+1][0] = r2_; a1f[s][p*2+1][1] = r3_;
        }
    u32 stf[2][4];
    #pragma unroll
    for (int s = 0; s < 2; s++)
        ldsm4(stf[s][0], stf[s][1], stf[s][2], stf[s][3], sSt + offM + s*32);

    __half hv[16];
    #pragma unroll
    for (int j = 0; j < 4; j++) {
        float c0 = 0.f, c1 = 0.f, c2 = 0.f, c3 = 0.f;
        mma16816(c0, c1, c2, c3, stf[0][0], stf[0][1], stf[0][2], stf[0][3],
                 a1f[0][j][0], a1f[0][j][1]);
        mma16816(c0, c1, c2, c3, stf[1][0], stf[1][1], stf[1][2], stf[1][3],
                 a1f[1][j][0], a1f[1][j][1]);
        int col = 8*j + cbase;
        float m0 = mbss[wid*32 + col];
        float m1 = mbss[wid*32 + col + 1];
        hv[4*j + 0] = __float2half_rn(c0 + m0);
        hv[4*j + 1] = __float2half_rn(c1 + m1);
        hv[4*j + 2] = (r0 < 4) ? __float2half_rn(c2 + m0) : __half(0.f);
        hv[4*j + 3] = (r0 < 4) ? __float2half_rn(c3 + m1) : __half(0.f);
    }
    uint4* gp = (uint4*)&g_P1mh[(size_t)nb*512 + lane*16];
    gp[0] = *(uint4*)&hv[0];
    gp[1] = *(uint4*)&hv[8];
}

// ---------------- L4: k_main — tensor cores; P1 via register LDG prefetch ----------------
#define PWB 6144
#define SMEM_MAIN (768 + 4*PWB)   // 25344 bytes

__global__ void __launch_bounds__(128, 5) k_main(const int* __restrict__ src,
                                                 const float* __restrict__ W_out,
                                                 const float* __restrict__ b_out,
                                                 float* __restrict__ out) {
    extern __shared__ __align__(16) char sh[];
    int* ekeys = (int*)sh;              // 96 ints
    int* slist = (int*)(sh + 384);      // 96 ints

    int t = threadIdx.x, wid = t >> 5, lane = t & 31;
    int n = blockIdx.x, b = wid;
    int nbd = n*4 + b;
    int es = g_offsets[n];
    int deg = g_offsets[n+1] - es;
    int degc = (deg < MAXDEG) ? deg : MAXDEG;

    if (t < degc) ekeys[t] = g_sorted[es + t];

    char* wb = sh + 768 + wid*PWB;
    __half* ssb = (__half*)wb;                 // 2 x 512 halves (ldmatrix A-layout ss)
    __half* A2b = (__half*)(wb + 2048);        // 2 x 1024 halves
    float*  news = (float*)(wb + 2048);        // alias over A2b after loop

    {
        const uint4* pb1 = (const uint4*)&g_B1h[(size_t)nbd*1024];
        #pragma unroll
        for (int i = lane; i < 128; i += 32) ((uint4*)A2b)[i] = pb1[i];
        const uint4* pdd = (const uint4*)&g_sth[(size_t)nbd*384];
        if (lane < 32) ((uint4*)ssb)[lane] = pdd[lane];
        if (lane < 16) ((uint4*)ssb)[32 + lane] = pdd[32 + lane];
        uint4 z = {0,0,0,0};
        if (lane < 16) ((uint4*)ssb)[48 + lane] = z;
        if (lane < 16) ((uint4*)(ssb + 512))[48 + lane] = z;
    }
    __syncwarp();

    int qr = lane & 7, q = lane >> 3;
    u32 offM = (u32)((qr + (q & 1)*8)*64 + (q >> 1)*16);
    int r0 = lane >> 2;
    int cbase = 2*(lane & 3);

    u32 sSS = (u32)__cvta_generic_to_shared(ssb);
    u32 sA2 = (u32)__cvta_generic_to_shared(A2b);

    u32 b1f[2][4][2];
    #pragma unroll
    for (int s = 0; s < 2; s++)
        #pragma unroll
        for (int p = 0; p < 2; p++) {
            u32 r0_, r1_, r2_, r3_;
            ldsm4t(r0_, r1_, r2_, r3_, sA2 + offM + s*1024 + p*32);
            b1f[s][p*2][0] = r0_;   b1f[s][p*2][1] = r1_;
            b1f[s][p*2+1][0] = r2_; b1f[s][p*2+1][1] = r3_;
        }
    u32 ddf[2][4];
    #pragma unroll
    for (int s = 0; s < 2; s++)
        ldsm4(ddf[s][0], ddf[s][1], ddf[s][2], ddf[s][3], sSS + offM + s*32);

    __syncthreads();
    if (t < degc) {
        int key = ekeys[t], r = 0;
        for (int j = 0; j < degc; j++) r += (ekeys[j] < key);
        slist[r] = src[key];
    }
    __syncthreads();

    float den[4][4], num[4][4];
    #pragma unroll
    for (int j = 0; j < 4; j++)
        #pragma unroll
        for (int i = 0; i < 4; i++) { den[j][i] = 0.f; num[j][i] = 0.f; }

    uint4 p1r[2];

    auto stageEdge = [&](int nbs, int v) {
        const char* pa = (const char*)&g_A2h[(size_t)nbs*1024];
        u32 da = sA2 + v*2048;
        #pragma unroll
        for (int r = 0; r < 4; r++) {
            int c = lane + 32*r;
            cpa16(da + c*16, pa + c*16);
        }
        const char* ps = (const char*)&g_sth[(size_t)nbs*384];
        u32 dsa = sSS + v*1024;
        cpa16(dsa + lane*16, ps + lane*16);
        if (lane < 16) cpa16(dsa + (32+lane)*16, ps + (32+lane)*16);
    };

    auto computeEdge = [&](int v) {
        u32 ssbase = sSS + v*1024;
        u32 a2base = sA2 + v*2048;
        u32 ssf[2][4];
        #pragma unroll
        for (int s = 0; s < 2; s++)
            ldsm4(ssf[s][0], ssf[s][1], ssf[s][2], ssf[s][3], ssbase + offM + s*32);
        u32 a2f[2][4][2];
        #pragma unroll
        for (int s = 0; s < 2; s++)
            #pragma unroll
            for (int p = 0; p < 2; p++) {
                u32 r0_, r1_, r2_, r3_;
                ldsm4t(r0_, r1_, r2_, r3_, a2base + offM + s*1024 + p*32);
                a2f[s][p*2][0] = r0_;   a2f[s][p*2][1] = r1_;
                a2f[s][p*2+1][0] = r2_; a2f[s][p*2+1][1] = r3_;
            }
        const __half2* ph = (const __half2*)p1r;
        #pragma unroll
        for (int j = 0; j < 4; j++) {
            float c0 = 0.f, c1 = 0.f, c2 = 0.f, c3 = 0.f;
            mma16816(c0, c1, c2, c3, ssf[0][0], ssf[0][1], ssf[0][2], ssf[0][3],
                     b1f[0][j][0], b1f[0][j][1]);
            mma16816(c0, c1, c2, c3, ssf[1][0], ssf[1][1], ssf[1][2], ssf[1][3],
                     b1f[1][j][0], b1f[1][j][1]);
            mma16816(c0, c1, c2, c3, ddf[0][0], ddf[0][1], ddf[0][2], ddf[0][3],
                     a2f[0][j][0], a2f[0][j][1]);
            mma16816(c0, c1, c2, c3, ddf[1][0], ddf[1][1], ddf[1][2], ddf[1][3],
                     a2f[1][j][0], a2f[1][j][1]);
            float2 pa_ = __half22float2(ph[2*j]);
            float2 pb_ = __half22float2(ph[2*j + 1]);
            u32 sa_ = ssf[j >> 1][(j & 1)*2];
            u32 sb_ = ssf[j >> 1][(j & 1)*2 + 1];
            float2 fa = __half22float2(*reinterpret_cast<__half2*>(&sa_));
            float2 fb = __half22float2(*reinterpret_cast<__half2*>(&sb_));
            float w0 = __expf(c0 + pa_.x);
            float w1 = __expf(c1 + pa_.y);
            float w2 = __expf(c2 + pb_.x);
            float w3 = __expf(c3 + pb_.y);
            den[j][0] += w0; den[j][1] += w1; den[j][2] += w2; den[j][3] += w3;
            num[j][0] = fmaf(w0, fa.x, num[j][0]);
            num[j][1] = fmaf(w1, fa.y, num[j][1]);
            num[j][2] = fmaf(w2, fb.x, num[j][2]);
            num[j][3] = fmaf(w3, fb.y, num[j][3]);
        }
    };

    for (int m = 0; m < degc + 1; m++) {
        if (m < degc) {
            stageEdge(slist[m]*4 + b, m & 1);
            cpcommit();
        }
        if (m > 0) {
            if (m < degc) cpwait<1>(); else cpwait<0>();
            __syncwarp();
            computeEdge((m - 1) & 1);
            __syncwarp();
        }
        if (m < degc) {
            int nbs = slist[m]*4 + b;
            const uint4* pp = (const uint4*)&g_P1mh[(size_t)nbs*512] + lane*2;
            p1r[0] = __ldg(pp);
            p1r[1] = __ldg(pp + 1);
        }
    }

    for (int i = MAXDEG; i < deg; i++) {
        int nbs = src[g_sorted[es + i]]*4 + b;
        stageEdge(nbs, 0);
        cpcommit();
        cpwait<0>();
        const uint4* pp = (const uint4*)&g_P1mh[(size_t)nbs*512] + lane*2;
        p1r[0] = __ldg(pp);
        p1r[1] = __ldg(pp + 1);
        __syncwarp();
        computeEdge(0);
        __syncwarp();
    }
    __syncwarp();

    #pragma unroll
    for (int j = 0; j < 4; j++) {
        int col = 8*j + cbase;
        float d0 = den[j][0], d1 = den[j][1], d2 = den[j][2], d3 = den[j][3];
        float2 lo;
        lo.x = __fdividef(num[j][0], d0 == 0.f ? 1.f : d0);
        lo.y = __fdividef(num[j][1], d1 == 0.f ? 1.f : d1);
        *(float2*)&news[r0*32 + col] = lo;
        if (r0 < 4) {
            float2 hi;
            hi.x = __fdividef(num[j][2], d2 == 0.f ? 1.f : d2);
            hi.y = __fdividef(num[j][3], d3 == 0.f ? 1.f : d3);
            *(float2*)&news[(r0+8)*32 + col] = hi;
        }
    }
    __syncwarp();

    for (int oi = lane; oi < L1D*OUTD; oi += 32) {
        int l = oi >> 4, o = oi & 15;
        float acc = __ldg(&b_out[o]);
        #pragma unroll
        for (int h = 0; h < HID; h++)
            acc = fmaf(news[l*32 + h], __ldg(&W_out[h*16 + o]), acc);
        out[((b*L1D + l)*N_NODES + n)*OUTD + o] = acc;
    }
}

// ---------------- launch ----------------
extern "C" void kernel_launch(void* const* d_in, const int* in_sizes, int n_in,
                              void* d_out, int out_size) {
    const float* long_states = (const float*)d_in[0];
    const float* short_in    = (const float*)d_in[1];
    const int*   src         = (const int*)d_in[2];
    const int*   dst         = (const int*)d_in[3];
    const float* W_in        = (const float*)d_in[4];
    const float* b_in        = (const float*)d_in[5];
    const float* W_metaW     = (const float*)d_in[6];
    const float* b_metaW     = (const float*)d_in[7];
    const float* W_metab     = (const float*)d_in[8];
    const float* b_metab     = (const float*)d_in[9];
    const float* W_out       = (const float*)d_in[10];
    const float* b_out       = (const float*)d_in[11];
    float* out = (float*)d_out;

    cudaFuncSetAttribute(k_main, cudaFuncAttributeMaxDynamicSharedMemorySize, SMEM_MAIN);

    k_statehistmeta<<<N_NODES + 4000, 128>>>(short_in, W_in, b_in, dst,
                                             long_states, W_metaW, b_metaW);
    k_scan<<<1, 1024>>>();
    k_pmbscatter<<<N_NODES, 128>>>(dst, long_states, W_metab, b_metab);
    k_main<<<N_NODES, 128, SMEM_MAIN>>>(src, W_out, b_out, out);
}